// round 1
// baseline (speedup 1.0000x reference)
#include <cuda_runtime.h>
#include <cstdint>
#include <cstddef>

// Problem constants
#define B_   2
#define S_   2048
#define H_   2048
#define NH_  16
#define NKV_ 4
#define D_   128
#define MROWS (B_*S_)          // 4096

// ---------------------------------------------------------------------------
// Scratch (device globals: no allocation allowed in kernel_launch)
// ---------------------------------------------------------------------------
__device__ float g_q  [(size_t)MROWS * (NH_*D_)];    // (4096, 2048)  q proj (RoPE'd in place)
__device__ float g_kv [(size_t)MROWS * (2*NKV_*D_)]; // (4096, 1024)  k | v
__device__ float g_att[(size_t)MROWS * (NH_*D_)];    // (4096, 2048)  attention output

// ---------------------------------------------------------------------------
// GEMM: C[M,N] = A[M,K] @ W[K,N], row-major fp32.
// 128x128 block tile, BK=16, 256 threads, 8x8 per-thread register tile.
// Per-thread cols are split {tc*4..+3} and {64+tc*4..+3} for conflict-free LDS.128.
// ---------------------------------------------------------------------------
__global__ __launch_bounds__(256, 2)
void gemm_kernel(const float* __restrict__ A, const float* __restrict__ W,
                 float* __restrict__ C, int M, int N, int K)
{
    __shared__ float As[16][132];   // k-major transposed A tile (padded)
    __shared__ float Bs[16][128];

    const int tid = threadIdx.x;
    const int br  = blockIdx.y * 128;
    const int bc  = blockIdx.x * 128;
    const int tr  = (tid >> 4) * 8;     // 16 groups of 8 rows
    const int tc  = (tid & 15) * 4;     // 16 groups, split columns

    float acc[8][8];
#pragma unroll
    for (int i = 0; i < 8; i++)
#pragma unroll
        for (int j = 0; j < 8; j++) acc[i][j] = 0.f;

    for (int k0 = 0; k0 < K; k0 += 16) {
#pragma unroll
        for (int p = 0; p < 2; p++) {
            int idx = p * 256 + tid;
            // A tile: 128 rows x 16 k, each thread one float4 along k
            int r  = idx >> 2;
            int kq = (idx & 3) * 4;
            float4 av = *(const float4*)(A + (size_t)(br + r) * K + k0 + kq);
            As[kq + 0][r] = av.x;
            As[kq + 1][r] = av.y;
            As[kq + 2][r] = av.z;
            As[kq + 3][r] = av.w;
            // W tile: 16 rows x 128 n
            int wk = idx >> 5;
            int wn = (idx & 31) * 4;
            *(float4*)(&Bs[wk][wn]) =
                *(const float4*)(W + (size_t)(k0 + wk) * N + bc + wn);
        }
        __syncthreads();

#pragma unroll
        for (int kk = 0; kk < 16; kk++) {
            float a[8], bv[8];
            *(float4*)(a)     = *(float4*)(&As[kk][tr]);
            *(float4*)(a + 4) = *(float4*)(&As[kk][tr + 4]);
            *(float4*)(bv)     = *(float4*)(&Bs[kk][tc]);
            *(float4*)(bv + 4) = *(float4*)(&Bs[kk][64 + tc]);
#pragma unroll
            for (int i = 0; i < 8; i++)
#pragma unroll
                for (int j = 0; j < 8; j++)
                    acc[i][j] += a[i] * bv[j];
        }
        __syncthreads();
    }

#pragma unroll
    for (int i = 0; i < 8; i++) {
        float* crow = C + (size_t)(br + tr + i) * N + bc;
        *(float4*)(crow + tc)      = make_float4(acc[i][0], acc[i][1], acc[i][2], acc[i][3]);
        *(float4*)(crow + 64 + tc) = make_float4(acc[i][4], acc[i][5], acc[i][6], acc[i][7]);
    }
}

// ---------------------------------------------------------------------------
// RoPE (rotate-half), in place. One thread handles the pair (d, d+64).
// cos/sin tables are (S, 128) with duplicated halves -> one cos, one sin load.
// ---------------------------------------------------------------------------
__global__ void rope_kernel(float* __restrict__ buf, int nheads, int ld,
                            const float* __restrict__ cosT,
                            const float* __restrict__ sinT, int total)
{
    int idx = blockIdx.x * blockDim.x + threadIdx.x;
    if (idx >= total) return;
    int d  = idx & 63;
    int h  = (idx >> 6) % nheads;
    int bs = idx / (64 * nheads);
    int s  = bs & (S_ - 1);
    float* p = buf + (size_t)bs * ld + h * D_;
    float x1 = p[d];
    float x2 = p[d + 64];
    float c  = cosT[s * D_ + d];
    float sn = sinT[s * D_ + d];
    p[d]      = x1 * c - x2 * sn;
    p[d + 64] = x2 * c + x1 * sn;
}

// ---------------------------------------------------------------------------
// Flash attention.
//   Q layout: (b*S+q, h*128+d)   of g_q
//   K layout: (b*S+k, kvh*128+d) cols [0,512) of g_kv
//   V layout: same rows, cols [512,1024)
//   Out: g_att (b*S+q, h*128+d)
// 64 queries/block, 64 keys/tile, 256 threads.
// sq/sk stored d-major [d][64] with XOR swizzle on 4-row groups.
// ---------------------------------------------------------------------------
#define ATT_SMEM_FLOATS (128*64 + 128*64 + 64*128 + 64*68)
#define ATT_SMEM_BYTES  (ATT_SMEM_FLOATS * 4)

__global__ __launch_bounds__(256, 1)
void attn_kernel(const float* __restrict__ Q, const float* __restrict__ KV,
                 float* __restrict__ O, const int* __restrict__ seqlen)
{
    extern __shared__ float sm[];
    float* sq = sm;                 // [128][64] swizzled
    float* sk = sq + 128 * 64;      // [128][64] swizzled
    float* sv = sk + 128 * 64;      // [64][128]
    float* sp = sv + 64 * 128;      // [64][68]  (k-major P)

    const int tid = threadIdx.x;
    const int bh  = blockIdx.x;               // 0..31
    const int qt  = 31 - blockIdx.y;          // heavy tiles first
    const int b   = bh >> 4;
    const int h   = bh & 15;
    const int kvh = h >> 2;
    const int q0  = qt * 64;
    const int len = seqlen[b];

    const float scale = 0.08838834764831845f; // 1/sqrt(128)

    // ---- load Q tile (scaled) into swizzled smem ----
    const float* qbase = Q + ((size_t)(b * S_ + q0) * (NH_ * D_)) + h * D_;
#pragma unroll
    for (int p = 0; p < 8; p++) {
        int gidx = p * 256 + tid;
        int d4 = gidx & 31;
        int r  = gidx >> 5;               // 0..63
        float4 v = *(const float4*)(qbase + (size_t)r * (NH_ * D_) + d4 * 4);
        int d  = d4 * 4;
        int sw = d4 & 15;
        int base = (((r >> 2) ^ sw) << 2) + (r & 3);
        sq[(d + 0) * 64 + base] = v.x * scale;
        sq[(d + 1) * 64 + base] = v.y * scale;
        sq[(d + 2) * 64 + base] = v.z * scale;
        sq[(d + 3) * 64 + base] = v.w * scale;
    }

    const int tr = tid >> 4;   // 0..15 : 4 query rows tr*4..+3
    const int tc = tid & 15;   // 0..15 : score cols tc*4..+3 / AV d-cols split

    float m[4], l[4], acc[4][8];
#pragma unroll
    for (int i = 0; i < 4; i++) {
        m[i] = -1e30f; l[i] = 0.f;
#pragma unroll
        for (int j = 0; j < 8; j++) acc[i][j] = 0.f;
    }

    const int e = min(q0 + 64, len);          // >= 1 always (len >= 1)
    const int ntiles = (e + 63) >> 6;

    const float* kbase = KV + (size_t)(b * S_) * (2 * NKV_ * D_) + kvh * D_;

    for (int t = 0; t < ntiles; t++) {
        const int k0 = t * 64;
        __syncthreads();   // protect previous tile's smem reads

        // ---- load K (swizzled d-major) + V (k-major) tiles ----
#pragma unroll
        for (int p = 0; p < 8; p++) {
            int gidx = p * 256 + tid;
            int d4 = gidx & 31;
            int r  = gidx >> 5;
            const float* krow = kbase + (size_t)(k0 + r) * (2 * NKV_ * D_);
            float4 kv4 = *(const float4*)(krow + d4 * 4);
            int d  = d4 * 4;
            int sw = d4 & 15;
            int base = (((r >> 2) ^ sw) << 2) + (r & 3);
            sk[(d + 0) * 64 + base] = kv4.x;
            sk[(d + 1) * 64 + base] = kv4.y;
            sk[(d + 2) * 64 + base] = kv4.z;
            sk[(d + 3) * 64 + base] = kv4.w;
            float4 vv = *(const float4*)(krow + NKV_ * D_ + d4 * 4);
            *(float4*)(sv + r * 128 + d4 * 4) = vv;
        }
        __syncthreads();

        // ---- scores: S = Q K^T (64x64), per-thread 4x4 ----
        float sacc[4][4];
#pragma unroll
        for (int i = 0; i < 4; i++)
#pragma unroll
            for (int j = 0; j < 4; j++) sacc[i][j] = 0.f;

#pragma unroll 4
        for (int d = 0; d < 128; d++) {
            int sw = (d >> 2) & 15;
            float4 a4 = *(const float4*)(sq + d * 64 + ((tr ^ sw) << 2));
            float4 b4 = *(const float4*)(sk + d * 64 + ((tc ^ sw) << 2));
            float av[4] = {a4.x, a4.y, a4.z, a4.w};
            float bv[4] = {b4.x, b4.y, b4.z, b4.w};
#pragma unroll
            for (int i = 0; i < 4; i++)
#pragma unroll
                for (int j = 0; j < 4; j++)
                    sacc[i][j] += av[i] * bv[j];
        }

        // ---- mask + online softmax (row stats via 16-lane shuffles) ----
#pragma unroll
        for (int i = 0; i < 4; i++) {
            int qg = q0 + tr * 4 + i;
            float mx = -1e30f;
#pragma unroll
            for (int j = 0; j < 4; j++) {
                int kg = k0 + tc * 4 + j;
                bool valid = (kg <= qg) && (kg < len);
                float sc = valid ? sacc[i][j] : -1e30f;
                sacc[i][j] = sc;
                mx = fmaxf(mx, sc);
            }
#pragma unroll
            for (int off = 8; off >= 1; off >>= 1)
                mx = fmaxf(mx, __shfl_xor_sync(0xffffffffu, mx, off));
            float mn = fmaxf(m[i], mx);
            float f  = __expf(m[i] - mn);
            m[i] = mn;
            float sum = 0.f;
            float pv[4];
#pragma unroll
            for (int j = 0; j < 4; j++) {
                pv[j] = __expf(sacc[i][j] - mn);
                sum += pv[j];
            }
#pragma unroll
            for (int off = 8; off >= 1; off >>= 1)
                sum += __shfl_xor_sync(0xffffffffu, sum, off);
            l[i] = l[i] * f + sum;
#pragma unroll
            for (int j = 0; j < 8; j++) acc[i][j] *= f;
            // stage P (k-major) for the AV gemm
#pragma unroll
            for (int j = 0; j < 4; j++)
                sp[(tc * 4 + j) * 68 + tr * 4 + i] = pv[j];
        }
        __syncthreads();

        // ---- AV: O += P V (64x128), per-thread 4 rows x 8 d-cols (split) ----
#pragma unroll 2
        for (int k = 0; k < 64; k++) {
            float4 a4 = *(const float4*)(sp + k * 68 + (tr << 2));
            float4 b0 = *(const float4*)(sv + k * 128 + (tc << 2));
            float4 b1 = *(const float4*)(sv + k * 128 + 64 + (tc << 2));
            float av[4] = {a4.x, a4.y, a4.z, a4.w};
            float bv[8] = {b0.x, b0.y, b0.z, b0.w, b1.x, b1.y, b1.z, b1.w};
#pragma unroll
            for (int i = 0; i < 4; i++)
#pragma unroll
                for (int j = 0; j < 8; j++)
                    acc[i][j] += av[i] * bv[j];
        }
    }

    // ---- epilogue: normalize and store ----
    float* obase = O + ((size_t)(b * S_ + q0) * (NH_ * D_)) + h * D_;
#pragma unroll
    for (int i = 0; i < 4; i++) {
        float inv = 1.0f / l[i];
        float* row = obase + (size_t)(tr * 4 + i) * (NH_ * D_);
        *(float4*)(row + tc * 4) =
            make_float4(acc[i][0] * inv, acc[i][1] * inv, acc[i][2] * inv, acc[i][3] * inv);
        *(float4*)(row + 64 + tc * 4) =
            make_float4(acc[i][4] * inv, acc[i][5] * inv, acc[i][6] * inv, acc[i][7] * inv);
    }
}

// ---------------------------------------------------------------------------
// Launch
// ---------------------------------------------------------------------------
extern "C" void kernel_launch(void* const* d_in, const int* in_sizes, int n_in,
                              void* d_out, int out_size)
{
    const float* x    = (const float*)d_in[0];
    const int*   seq  = (const int*)  d_in[1];
    const float* fcos = (const float*)d_in[2];
    const float* fsin = (const float*)d_in[3];
    const float* Wq   = (const float*)d_in[4];
    const float* Wkv  = (const float*)d_in[5];
    const float* Wo   = (const float*)d_in[6];
    float* out = (float*)d_out;

    float *qp, *kvp, *ap;
    cudaGetSymbolAddress((void**)&qp,  g_q);
    cudaGetSymbolAddress((void**)&kvp, g_kv);
    cudaGetSymbolAddress((void**)&ap,  g_att);

    cudaFuncSetAttribute(attn_kernel,
                         cudaFuncAttributeMaxDynamicSharedMemorySize,
                         ATT_SMEM_BYTES);

    dim3 blk(256);

    // 1) projections
    gemm_kernel<<<dim3(16, 32), blk>>>(x, Wq,  qp,  MROWS, NH_ * D_,     H_);
    gemm_kernel<<<dim3(8,  32), blk>>>(x, Wkv, kvp, MROWS, 2 * NKV_ * D_, H_);

    // 2) RoPE on q and k (in place)
    {
        int tq = MROWS * NH_ * 64;   // 4,194,304
        int tk = MROWS * NKV_ * 64;  // 1,048,576
        rope_kernel<<<(tq + 255) / 256, 256>>>(qp,  NH_,  NH_ * D_,     fcos, fsin, tq);
        rope_kernel<<<(tk + 255) / 256, 256>>>(kvp, NKV_, 2 * NKV_ * D_, fcos, fsin, tk);
    }

    // 3) attention
    attn_kernel<<<dim3(32, 32), blk, ATT_SMEM_BYTES>>>(qp, kvp, ap, seq);

    // 4) output projection
    gemm_kernel<<<dim3(16, 32), blk>>>(ap, Wo, out, MROWS, H_, H_);
}

// round 3
// speedup vs baseline: 1.4769x; 1.4769x over previous
#include <cuda_runtime.h>
#include <cuda_bf16.h>
#include <cstdint>
#include <cstddef>

// Problem constants
#define B_   2
#define S_   2048
#define H_   2048
#define NH_  16
#define NKV_ 4
#define D_   128
#define MROWS (B_*S_)          // 4096

// ---------------------------------------------------------------------------
// PTX helpers (sm_100-safe: mma.sync / ldmatrix / cp.async only)
// ---------------------------------------------------------------------------
__device__ __forceinline__ uint32_t smem_to_u32(const void* p) {
    uint32_t a;
    asm("{ .reg .u64 t; cvta.to.shared.u64 t, %1; cvt.u32.u64 %0, t; }" : "=r"(a) : "l"(p));
    return a;
}
__device__ __forceinline__ void ldsm4(uint32_t* r, uint32_t addr) {
    asm volatile("ldmatrix.sync.aligned.m8n8.x4.shared.b16 {%0,%1,%2,%3}, [%4];"
        : "=r"(r[0]), "=r"(r[1]), "=r"(r[2]), "=r"(r[3]) : "r"(addr));
}
__device__ __forceinline__ void mma_bf16(float* d, const uint32_t* a, uint32_t b0, uint32_t b1) {
    asm volatile("mma.sync.aligned.m16n8k16.row.col.f32.bf16.bf16.f32 "
        "{%0,%1,%2,%3}, {%4,%5,%6,%7}, {%8,%9}, {%0,%1,%2,%3};"
        : "+f"(d[0]), "+f"(d[1]), "+f"(d[2]), "+f"(d[3])
        : "r"(a[0]), "r"(a[1]), "r"(a[2]), "r"(a[3]), "r"(b0), "r"(b1));
}
__device__ __forceinline__ void cpasync16(uint32_t saddr, const void* g) {
    asm volatile("cp.async.cg.shared.global [%0], [%1], 16;" :: "r"(saddr), "l"(g));
}
#define CP_COMMIT() asm volatile("cp.async.commit_group;" ::: "memory")
#define CP_WAIT(n)  asm volatile("cp.async.wait_group %0;" :: "n"(n) : "memory")

// ---------------------------------------------------------------------------
// Scratch (device globals)
// ---------------------------------------------------------------------------
__device__ float g_q  [(size_t)MROWS * (NH_*D_)];    // fp32 q proj (RoPE'd in place)
__device__ float g_kv [(size_t)MROWS * (2*NKV_*D_)]; // fp32 k | v
__device__ float g_att[(size_t)MROWS * (NH_*D_)];    // fp32 attention output

__device__ __nv_bfloat16 g_xhi[(size_t)MROWS * H_];
__device__ __nv_bfloat16 g_xlo[(size_t)MROWS * H_];
__device__ __nv_bfloat16 g_ahi[(size_t)MROWS * H_];
__device__ __nv_bfloat16 g_alo[(size_t)MROWS * H_];
__device__ __nv_bfloat16 g_wqh[(size_t)H_ * (NH_*D_)];   // [N,K] transposed
__device__ __nv_bfloat16 g_wql[(size_t)H_ * (NH_*D_)];
__device__ __nv_bfloat16 g_wkh[(size_t)H_ * (2*NKV_*D_)];
__device__ __nv_bfloat16 g_wkl[(size_t)H_ * (2*NKV_*D_)];
__device__ __nv_bfloat16 g_woh[(size_t)H_ * H_];
__device__ __nv_bfloat16 g_wol[(size_t)H_ * H_];

// ---------------------------------------------------------------------------
// split fp32 -> bf16 hi/lo (row-major, same layout). 8 elems/thread.
// ---------------------------------------------------------------------------
__global__ void split_kernel(const float* __restrict__ in,
                             __nv_bfloat16* __restrict__ hi,
                             __nv_bfloat16* __restrict__ lo, int n8)
{
    int idx = blockIdx.x * blockDim.x + threadIdx.x;
    if (idx >= n8) return;
    union { __nv_bfloat16 b[8]; uint4 u; } uh, ul;
    const float4* in4 = (const float4*)in;
#pragma unroll
    for (int q = 0; q < 2; q++) {
        float4 v = in4[idx * 2 + q];
        float f[4] = {v.x, v.y, v.z, v.w};
#pragma unroll
        for (int i = 0; i < 4; i++) {
            __nv_bfloat16 h = __float2bfloat16_rn(f[i]);
            uh.b[q * 4 + i] = h;
            ul.b[q * 4 + i] = __float2bfloat16_rn(f[i] - __bfloat162float(h));
        }
    }
    ((uint4*)hi)[idx] = uh.u;
    ((uint4*)lo)[idx] = ul.u;
}

// ---------------------------------------------------------------------------
// split + transpose: W[K,N] fp32 -> Thi/Tlo[N,K] bf16. 32x32 smem tiles.
// ---------------------------------------------------------------------------
__global__ void splitT_kernel(const float* __restrict__ W,
                              __nv_bfloat16* __restrict__ Thi,
                              __nv_bfloat16* __restrict__ Tlo, int K, int N)
{
    __shared__ float s[32][33];
    int tx = threadIdx.x, ty = threadIdx.y;           // (32, 8)
    int n0 = blockIdx.x * 32, k0 = blockIdx.y * 32;
#pragma unroll
    for (int i = 0; i < 4; i++) {
        int k = k0 + ty + i * 8;
        s[ty + i * 8][tx] = W[(size_t)k * N + n0 + tx];
    }
    __syncthreads();
#pragma unroll
    for (int i = 0; i < 4; i++) {
        int n = n0 + ty + i * 8;
        float v = s[tx][ty + i * 8];                   // W[k0+tx][n]
        __nv_bfloat16 h = __float2bfloat16_rn(v);
        Thi[(size_t)n * K + k0 + tx] = h;
        Tlo[(size_t)n * K + k0 + tx] = __float2bfloat16_rn(v - __bfloat162float(h));
    }
}

// ---------------------------------------------------------------------------
// mma.sync split-bf16 GEMM: C[M,N] = (Ahi+Alo)[M,K] @ (Bhi+Blo)[N,K]^T
// 128x128 CTA tile, BK=32, 8 warps (4x2 -> 32x64 warp tiles),
// 2-stage cp.async pipeline.
// smem per stage: Ah | Al | Bh | Bl, each 128 rows x 64B, XOR-swizzled.
// ---------------------------------------------------------------------------
#define STAGE_BYTES  32768
#define TILE_BYTES   8192
#define GEMM_SMEM_BYTES (2 * STAGE_BYTES)

__global__ __launch_bounds__(256, 1)
void gemm_mma(const __nv_bfloat16* __restrict__ Ahi, const __nv_bfloat16* __restrict__ Alo,
              const __nv_bfloat16* __restrict__ Bhi, const __nv_bfloat16* __restrict__ Blo,
              float* __restrict__ C, int M, int N, int K)
{
    extern __shared__ char smem[];
    const uint32_t sbase = smem_to_u32(smem);
    const int tid  = threadIdx.x;
    const int wid  = tid >> 5;
    const int lane = tid & 31;
    const int br = blockIdx.y * 128;
    const int bc = blockIdx.x * 128;
    const int wr = wid & 3;          // m: wr*32
    const int wc = wid >> 2;         // n: wc*64

    const int nchunks = K >> 5;      // BK=32

    // per-thread load slots: 2 units per tile (512 16B-units / 256 threads)
    // unit = 2*tid + {0,1}:  r = unit>>2, u = unit&3
    int r0u = (2 * tid) >> 2, u0 = (2 * tid) & 3;
    int r1u = (2 * tid + 1) >> 2, u1 = (2 * tid + 1) & 3;
    uint32_t so0 = (uint32_t)(r0u * 64 + (u0 ^ ((r0u >> 1) & 3)) * 16);
    uint32_t so1 = (uint32_t)(r1u * 64 + (u1 ^ ((r1u >> 1) & 3)) * 16);

    float acc[2][8][4];
#pragma unroll
    for (int i = 0; i < 2; i++)
#pragma unroll
        for (int j = 0; j < 8; j++)
#pragma unroll
            for (int q = 0; q < 4; q++) acc[i][j][q] = 0.f;

    // ldmatrix addresses (depend only on lane): row-in-tile + k-half
    const int arow0 = wr * 32 + (lane & 15);           // A m16 tile 0
    const int arow1 = arow0 + 16;                      // A m16 tile 1
    const int khalf = lane >> 4;                       // 0/1 -> 16B half

    auto issue_loads = [&](int c, int stage) {
        uint32_t sb = sbase + stage * STAGE_BYTES;
        const __nv_bfloat16* pAh = Ahi + (size_t)br * K + c * 32;
        const __nv_bfloat16* pAl = Alo + (size_t)br * K + c * 32;
        const __nv_bfloat16* pBh = Bhi + (size_t)bc * K + c * 32;
        const __nv_bfloat16* pBl = Blo + (size_t)bc * K + c * 32;
        size_t g0 = (size_t)r0u * K + u0 * 8;
        size_t g1 = (size_t)r1u * K + u1 * 8;
        cpasync16(sb + so0,                  pAh + g0);
        cpasync16(sb + so1,                  pAh + g1);
        cpasync16(sb + TILE_BYTES + so0,     pAl + g0);
        cpasync16(sb + TILE_BYTES + so1,     pAl + g1);
        cpasync16(sb + 2*TILE_BYTES + so0,   pBh + g0);
        cpasync16(sb + 2*TILE_BYTES + so1,   pBh + g1);
        cpasync16(sb + 3*TILE_BYTES + so0,   pBl + g0);
        cpasync16(sb + 3*TILE_BYTES + so1,   pBl + g1);
    };

    issue_loads(0, 0);
    CP_COMMIT();

    for (int c = 0; c < nchunks; c++) {
        if (c + 1 < nchunks) {
            issue_loads(c + 1, (c + 1) & 1);
            CP_COMMIT();
            CP_WAIT(1);
        } else {
            CP_WAIT(0);
        }
        __syncthreads();

        uint32_t sA = sbase + (c & 1) * STAGE_BYTES;
        uint32_t sB = sA + 2 * TILE_BYTES;

#pragma unroll
        for (int kk = 0; kk < 2; kk++) {
            // A fragments (hi & lo) for 2 m16 tiles
            uint32_t ah[2][4], al[2][4];
#pragma unroll
            for (int mt = 0; mt < 2; mt++) {
                int row = (mt ? arow1 : arow0);
                int cc  = (kk * 2 + khalf) ^ ((row >> 1) & 3);
                uint32_t ad = sA + (uint32_t)(row * 64 + cc * 16);
                ldsm4(ah[mt], ad);
                ldsm4(al[mt], ad + TILE_BYTES);
            }
            // B fragments (hi & lo) for 4 n16 groups
            uint32_t bh[4][4], bl[4][4];
#pragma unroll
            for (int ng = 0; ng < 4; ng++) {
                int row = wc * 64 + ng * 16 + (lane & 15);
                int cc  = (kk * 2 + khalf) ^ ((row >> 1) & 3);
                uint32_t bd = sB + (uint32_t)(row * 64 + cc * 16);
                ldsm4(bh[ng], bd);
                ldsm4(bl[ng], bd + TILE_BYTES);
            }
            // MMA: hi*hi + hi*lo + lo*hi
#pragma unroll
            for (int mt = 0; mt < 2; mt++)
#pragma unroll
                for (int j = 0; j < 8; j++) {
                    int ng = j >> 1, hf = j & 1;
                    mma_bf16(acc[mt][j], ah[mt], bh[ng][hf], bh[ng][2 + hf]);
                    mma_bf16(acc[mt][j], ah[mt], bl[ng][hf], bl[ng][2 + hf]);
                    mma_bf16(acc[mt][j], al[mt], bh[ng][hf], bh[ng][2 + hf]);
                }
        }
        __syncthreads();
    }

    // ---- epilogue: direct float2 stores ----
#pragma unroll
    for (int mt = 0; mt < 2; mt++) {
        int row = br + wr * 32 + mt * 16 + (lane >> 2);
#pragma unroll
        for (int j = 0; j < 8; j++) {
            int col = bc + wc * 64 + j * 8 + (lane & 3) * 2;
            *(float2*)(C + (size_t)row * N + col) =
                make_float2(acc[mt][j][0], acc[mt][j][1]);
            *(float2*)(C + (size_t)(row + 8) * N + col) =
                make_float2(acc[mt][j][2], acc[mt][j][3]);
        }
    }
}

// ---------------------------------------------------------------------------
// RoPE (rotate-half), in place.
// ---------------------------------------------------------------------------
__global__ void rope_kernel(float* __restrict__ buf, int nheads, int ld,
                            const float* __restrict__ cosT,
                            const float* __restrict__ sinT, int total)
{
    int idx = blockIdx.x * blockDim.x + threadIdx.x;
    if (idx >= total) return;
    int d  = idx & 63;
    int h  = (idx >> 6) % nheads;
    int bs = idx / (64 * nheads);
    int s  = bs & (S_ - 1);
    float* p = buf + (size_t)bs * ld + h * D_;
    float x1 = p[d];
    float x2 = p[d + 64];
    float c  = cosT[s * D_ + d];
    float sn = sinT[s * D_ + d];
    p[d]      = x1 * c - x2 * sn;
    p[d + 64] = x2 * c + x1 * sn;
}

// ---------------------------------------------------------------------------
// Flash attention (fp32 SIMT, unchanged from R1).
// ---------------------------------------------------------------------------
#define ATT_SMEM_FLOATS (128*64 + 128*64 + 64*128 + 64*68)
#define ATT_SMEM_BYTES  (ATT_SMEM_FLOATS * 4)

__global__ __launch_bounds__(256, 1)
void attn_kernel(const float* __restrict__ Q, const float* __restrict__ KV,
                 float* __restrict__ O, const int* __restrict__ seqlen)
{
    extern __shared__ float sm[];
    float* sq = sm;                 // [128][64] swizzled
    float* sk = sq + 128 * 64;      // [128][64] swizzled
    float* sv = sk + 128 * 64;      // [64][128]
    float* sp = sv + 64 * 128;      // [64][68]  (k-major P)

    const int tid = threadIdx.x;
    const int bh  = blockIdx.x;               // 0..31
    const int qt  = 31 - blockIdx.y;          // heavy tiles first
    const int b   = bh >> 4;
    const int h   = bh & 15;
    const int kvh = h >> 2;
    const int q0  = qt * 64;
    const int len = seqlen[b];

    const float scale = 0.08838834764831845f; // 1/sqrt(128)

    const float* qbase = Q + ((size_t)(b * S_ + q0) * (NH_ * D_)) + h * D_;
#pragma unroll
    for (int p = 0; p < 8; p++) {
        int gidx = p * 256 + tid;
        int d4 = gidx & 31;
        int r  = gidx >> 5;
        float4 v = *(const float4*)(qbase + (size_t)r * (NH_ * D_) + d4 * 4);
        int d  = d4 * 4;
        int sw = d4 & 15;
        int base = (((r >> 2) ^ sw) << 2) + (r & 3);
        sq[(d + 0) * 64 + base] = v.x * scale;
        sq[(d + 1) * 64 + base] = v.y * scale;
        sq[(d + 2) * 64 + base] = v.z * scale;
        sq[(d + 3) * 64 + base] = v.w * scale;
    }

    const int tr = tid >> 4;
    const int tc = tid & 15;

    float m[4], l[4], acc[4][8];
#pragma unroll
    for (int i = 0; i < 4; i++) {
        m[i] = -1e30f; l[i] = 0.f;
#pragma unroll
        for (int j = 0; j < 8; j++) acc[i][j] = 0.f;
    }

    const int e = min(q0 + 64, len);
    const int ntiles = (e + 63) >> 6;

    const float* kbase = KV + (size_t)(b * S_) * (2 * NKV_ * D_) + kvh * D_;

    for (int t = 0; t < ntiles; t++) {
        const int k0 = t * 64;
        __syncthreads();

#pragma unroll
        for (int p = 0; p < 8; p++) {
            int gidx = p * 256 + tid;
            int d4 = gidx & 31;
            int r  = gidx >> 5;
            const float* krow = kbase + (size_t)(k0 + r) * (2 * NKV_ * D_);
            float4 kv4 = *(const float4*)(krow + d4 * 4);
            int d  = d4 * 4;
            int sw = d4 & 15;
            int base = (((r >> 2) ^ sw) << 2) + (r & 3);
            sk[(d + 0) * 64 + base] = kv4.x;
            sk[(d + 1) * 64 + base] = kv4.y;
            sk[(d + 2) * 64 + base] = kv4.z;
            sk[(d + 3) * 64 + base] = kv4.w;
            float4 vv = *(const float4*)(krow + NKV_ * D_ + d4 * 4);
            *(float4*)(sv + r * 128 + d4 * 4) = vv;
        }
        __syncthreads();

        float sacc[4][4];
#pragma unroll
        for (int i = 0; i < 4; i++)
#pragma unroll
            for (int j = 0; j < 4; j++) sacc[i][j] = 0.f;

#pragma unroll 4
        for (int d = 0; d < 128; d++) {
            int sw = (d >> 2) & 15;
            float4 a4 = *(const float4*)(sq + d * 64 + ((tr ^ sw) << 2));
            float4 b4 = *(const float4*)(sk + d * 64 + ((tc ^ sw) << 2));
            float av[4] = {a4.x, a4.y, a4.z, a4.w};
            float bv[4] = {b4.x, b4.y, b4.z, b4.w};
#pragma unroll
            for (int i = 0; i < 4; i++)
#pragma unroll
                for (int j = 0; j < 4; j++)
                    sacc[i][j] += av[i] * bv[j];
        }

#pragma unroll
        for (int i = 0; i < 4; i++) {
            int qg = q0 + tr * 4 + i;
            float mx = -1e30f;
#pragma unroll
            for (int j = 0; j < 4; j++) {
                int kg = k0 + tc * 4 + j;
                bool valid = (kg <= qg) && (kg < len);
                float sc = valid ? sacc[i][j] : -1e30f;
                sacc[i][j] = sc;
                mx = fmaxf(mx, sc);
            }
#pragma unroll
            for (int off = 8; off >= 1; off >>= 1)
                mx = fmaxf(mx, __shfl_xor_sync(0xffffffffu, mx, off));
            float mn = fmaxf(m[i], mx);
            float f  = __expf(m[i] - mn);
            m[i] = mn;
            float sum = 0.f;
            float pv[4];
#pragma unroll
            for (int j = 0; j < 4; j++) {
                pv[j] = __expf(sacc[i][j] - mn);
                sum += pv[j];
            }
#pragma unroll
            for (int off = 8; off >= 1; off >>= 1)
                sum += __shfl_xor_sync(0xffffffffu, sum, off);
            l[i] = l[i] * f + sum;
#pragma unroll
            for (int j = 0; j < 8; j++) acc[i][j] *= f;
#pragma unroll
            for (int j = 0; j < 4; j++)
                sp[(tc * 4 + j) * 68 + tr * 4 + i] = pv[j];
        }
        __syncthreads();

#pragma unroll 2
        for (int k = 0; k < 64; k++) {
            float4 a4 = *(const float4*)(sp + k * 68 + (tr << 2));
            float4 b0 = *(const float4*)(sv + k * 128 + (tc << 2));
            float4 b1 = *(const float4*)(sv + k * 128 + 64 + (tc << 2));
            float av[4] = {a4.x, a4.y, a4.z, a4.w};
            float bv[8] = {b0.x, b0.y, b0.z, b0.w, b1.x, b1.y, b1.z, b1.w};
#pragma unroll
            for (int i = 0; i < 4; i++)
#pragma unroll
                for (int j = 0; j < 8; j++)
                    acc[i][j] += av[i] * bv[j];
        }
    }

    float* obase = O + ((size_t)(b * S_ + q0) * (NH_ * D_)) + h * D_;
#pragma unroll
    for (int i = 0; i < 4; i++) {
        float inv = 1.0f / l[i];
        float* row = obase + (size_t)(tr * 4 + i) * (NH_ * D_);
        *(float4*)(row + tc * 4) =
            make_float4(acc[i][0] * inv, acc[i][1] * inv, acc[i][2] * inv, acc[i][3] * inv);
        *(float4*)(row + 64 + tc * 4) =
            make_float4(acc[i][4] * inv, acc[i][5] * inv, acc[i][6] * inv, acc[i][7] * inv);
    }
}

// ---------------------------------------------------------------------------
// Launch
// ---------------------------------------------------------------------------
extern "C" void kernel_launch(void* const* d_in, const int* in_sizes, int n_in,
                              void* d_out, int out_size)
{
    const float* x    = (const float*)d_in[0];
    const int*   seq  = (const int*)  d_in[1];
    const float* fcos = (const float*)d_in[2];
    const float* fsin = (const float*)d_in[3];
    const float* Wq   = (const float*)d_in[4];
    const float* Wkv  = (const float*)d_in[5];
    const float* Wo   = (const float*)d_in[6];
    float* out = (float*)d_out;

    float *qp, *kvp, *ap;
    cudaGetSymbolAddress((void**)&qp,  g_q);
    cudaGetSymbolAddress((void**)&kvp, g_kv);
    cudaGetSymbolAddress((void**)&ap,  g_att);
    __nv_bfloat16 *xhi, *xlo, *ahi, *alo, *wqh, *wql, *wkh, *wkl, *woh, *wol;
    cudaGetSymbolAddress((void**)&xhi, g_xhi);
    cudaGetSymbolAddress((void**)&xlo, g_xlo);
    cudaGetSymbolAddress((void**)&ahi, g_ahi);
    cudaGetSymbolAddress((void**)&alo, g_alo);
    cudaGetSymbolAddress((void**)&wqh, g_wqh);
    cudaGetSymbolAddress((void**)&wql, g_wql);
    cudaGetSymbolAddress((void**)&wkh, g_wkh);
    cudaGetSymbolAddress((void**)&wkl, g_wkl);
    cudaGetSymbolAddress((void**)&woh, g_woh);
    cudaGetSymbolAddress((void**)&wol, g_wol);

    cudaFuncSetAttribute(attn_kernel, cudaFuncAttributeMaxDynamicSharedMemorySize, ATT_SMEM_BYTES);
    cudaFuncSetAttribute(gemm_mma,    cudaFuncAttributeMaxDynamicSharedMemorySize, GEMM_SMEM_BYTES);

    dim3 blk(256);

    // 0) precision-split preprocessing
    {
        int n8 = MROWS * H_ / 8;
        split_kernel<<<(n8 + 255) / 256, 256>>>(x, xhi, xlo, n8);
        dim3 tb(32, 8);
        splitT_kernel<<<dim3((NH_*D_)/32,    H_/32), tb>>>(Wq,  wqh, wql, H_, NH_*D_);
        splitT_kernel<<<dim3((2*NKV_*D_)/32, H_/32), tb>>>(Wkv, wkh, wkl, H_, 2*NKV_*D_);
        splitT_kernel<<<dim3(H_/32,          H_/32), tb>>>(Wo,  woh, wol, H_, H_);
    }

    // 1) projections (mma.sync split-bf16)
    gemm_mma<<<dim3(16, 32), blk, GEMM_SMEM_BYTES>>>(xhi, xlo, wqh, wql, qp,  MROWS, NH_*D_,    H_);
    gemm_mma<<<dim3(8,  32), blk, GEMM_SMEM_BYTES>>>(xhi, xlo, wkh, wkl, kvp, MROWS, 2*NKV_*D_, H_);

    // 2) RoPE on q and k (in place)
    {
        int tq = MROWS * NH_ * 64;
        int tk = MROWS * NKV_ * 64;
        rope_kernel<<<(tq + 255) / 256, 256>>>(qp,  NH_,  NH_ * D_,      fcos, fsin, tq);
        rope_kernel<<<(tk + 255) / 256, 256>>>(kvp, NKV_, 2 * NKV_ * D_, fcos, fsin, tk);
    }

    // 3) attention (fp32 SIMT)
    attn_kernel<<<dim3(32, 32), blk, ATT_SMEM_BYTES>>>(qp, kvp, ap, seq);

    // 4) output projection (split attention output first)
    {
        int n8 = MROWS * H_ / 8;
        split_kernel<<<(n8 + 255) / 256, 256>>>(ap, ahi, alo, n8);
    }
    gemm_mma<<<dim3(16, 32), blk, GEMM_SMEM_BYTES>>>(ahi, alo, woh, wol, out, MROWS, H_, H_);
}

// round 5
// speedup vs baseline: 2.1928x; 1.4848x over previous
#include <cuda_runtime.h>
#include <cuda_bf16.h>
#include <cstdint>
#include <cstddef>

// Problem constants
#define B_   2
#define S_   2048
#define H_   2048
#define NH_  16
#define NKV_ 4
#define D_   128
#define MROWS (B_*S_)          // 4096
#define QSCALE 0.08838834764831845f

// ---------------------------------------------------------------------------
// PTX helpers (sm_100-safe: mma.sync / ldmatrix / cp.async only)
// ---------------------------------------------------------------------------
__device__ __forceinline__ uint32_t smem_to_u32(const void* p) {
    uint32_t a;
    asm("{ .reg .u64 t; cvta.to.shared.u64 t, %1; cvt.u32.u64 %0, t; }" : "=r"(a) : "l"(p));
    return a;
}
__device__ __forceinline__ void ldsm4(uint32_t* r, uint32_t addr) {
    asm volatile("ldmatrix.sync.aligned.m8n8.x4.shared.b16 {%0,%1,%2,%3}, [%4];"
        : "=r"(r[0]), "=r"(r[1]), "=r"(r[2]), "=r"(r[3]) : "r"(addr));
}
__device__ __forceinline__ void ldsm4t(uint32_t* r, uint32_t addr) {
    asm volatile("ldmatrix.sync.aligned.m8n8.x4.trans.shared.b16 {%0,%1,%2,%3}, [%4];"
        : "=r"(r[0]), "=r"(r[1]), "=r"(r[2]), "=r"(r[3]) : "r"(addr));
}
__device__ __forceinline__ void mma_bf16(float* d, const uint32_t* a, uint32_t b0, uint32_t b1) {
    asm volatile("mma.sync.aligned.m16n8k16.row.col.f32.bf16.bf16.f32 "
        "{%0,%1,%2,%3}, {%4,%5,%6,%7}, {%8,%9}, {%0,%1,%2,%3};"
        : "+f"(d[0]), "+f"(d[1]), "+f"(d[2]), "+f"(d[3])
        : "r"(a[0]), "r"(a[1]), "r"(a[2]), "r"(a[3]), "r"(b0), "r"(b1));
}
__device__ __forceinline__ void cpasync16(uint32_t saddr, const void* g) {
    asm volatile("cp.async.cg.shared.global [%0], [%1], 16;" :: "r"(saddr), "l"(g));
}
#define CP_COMMIT() asm volatile("cp.async.commit_group;" ::: "memory")
#define CP_WAIT(n)  asm volatile("cp.async.wait_group %0;" :: "n"(n) : "memory")

__device__ __forceinline__ void split2pack(float a, float b, uint32_t& hi, uint32_t& lo) {
    __nv_bfloat16 ah = __float2bfloat16_rn(a);
    __nv_bfloat16 bh = __float2bfloat16_rn(b);
    __nv_bfloat16 al = __float2bfloat16_rn(a - __bfloat162float(ah));
    __nv_bfloat16 bl = __float2bfloat16_rn(b - __bfloat162float(bh));
    hi = (uint32_t)(*(uint16_t*)&ah) | ((uint32_t)(*(uint16_t*)&bh) << 16);
    lo = (uint32_t)(*(uint16_t*)&al) | ((uint32_t)(*(uint16_t*)&bl) << 16);
}

// ---------------------------------------------------------------------------
// Scratch (device globals)
// ---------------------------------------------------------------------------
__device__ float g_q  [(size_t)MROWS * (NH_*D_)];    // fp32 q proj
__device__ float g_kv [(size_t)MROWS * (2*NKV_*D_)]; // fp32 k | v
__device__ float g_att[(size_t)MROWS * (NH_*D_)];    // fp32 attention output

__device__ __nv_bfloat16 g_xhi[(size_t)MROWS * H_];
__device__ __nv_bfloat16 g_xlo[(size_t)MROWS * H_];
__device__ __nv_bfloat16 g_ahi[(size_t)MROWS * H_];
__device__ __nv_bfloat16 g_alo[(size_t)MROWS * H_];
__device__ __nv_bfloat16 g_wqh[(size_t)H_ * (NH_*D_)];   // [N,K] transposed
__device__ __nv_bfloat16 g_wql[(size_t)H_ * (NH_*D_)];
__device__ __nv_bfloat16 g_wkh[(size_t)H_ * (2*NKV_*D_)];
__device__ __nv_bfloat16 g_wkl[(size_t)H_ * (2*NKV_*D_)];
__device__ __nv_bfloat16 g_woh[(size_t)H_ * H_];
__device__ __nv_bfloat16 g_wol[(size_t)H_ * H_];
// attention operands (bf16 hi/lo)
__device__ __nv_bfloat16 g_qhi[(size_t)MROWS * (NH_*D_)];
__device__ __nv_bfloat16 g_qlo[(size_t)MROWS * (NH_*D_)];
__device__ __nv_bfloat16 g_khi[(size_t)MROWS * (NKV_*D_)];
__device__ __nv_bfloat16 g_klo[(size_t)MROWS * (NKV_*D_)];
__device__ __nv_bfloat16 g_vhi[(size_t)MROWS * (NKV_*D_)];
__device__ __nv_bfloat16 g_vlo[(size_t)MROWS * (NKV_*D_)];

// ---------------------------------------------------------------------------
// split fp32 -> bf16 hi/lo (row-major, same layout). 8 elems/thread.
// ---------------------------------------------------------------------------
__global__ void split_kernel(const float* __restrict__ in,
                             __nv_bfloat16* __restrict__ hi,
                             __nv_bfloat16* __restrict__ lo, int n8)
{
    int idx = blockIdx.x * blockDim.x + threadIdx.x;
    if (idx >= n8) return;
    union { __nv_bfloat16 b[8]; uint4 u; } uh, ul;
    const float4* in4 = (const float4*)in;
#pragma unroll
    for (int q = 0; q < 2; q++) {
        float4 v = in4[idx * 2 + q];
        float f[4] = {v.x, v.y, v.z, v.w};
#pragma unroll
        for (int i = 0; i < 4; i++) {
            __nv_bfloat16 h = __float2bfloat16_rn(f[i]);
            uh.b[q * 4 + i] = h;
            ul.b[q * 4 + i] = __float2bfloat16_rn(f[i] - __bfloat162float(h));
        }
    }
    ((uint4*)hi)[idx] = uh.u;
    ((uint4*)lo)[idx] = ul.u;
}

// ---------------------------------------------------------------------------
// split + transpose: W[K,N] fp32 -> Thi/Tlo[N,K] bf16. 32x32 smem tiles.
// ---------------------------------------------------------------------------
__global__ void splitT_kernel(const float* __restrict__ W,
                              __nv_bfloat16* __restrict__ Thi,
                              __nv_bfloat16* __restrict__ Tlo, int K, int N)
{
    __shared__ float s[32][33];
    int tx = threadIdx.x, ty = threadIdx.y;           // (32, 8)
    int n0 = blockIdx.x * 32, k0 = blockIdx.y * 32;
#pragma unroll
    for (int i = 0; i < 4; i++) {
        int k = k0 + ty + i * 8;
        s[ty + i * 8][tx] = W[(size_t)k * N + n0 + tx];
    }
    __syncthreads();
#pragma unroll
    for (int i = 0; i < 4; i++) {
        int n = n0 + ty + i * 8;
        float v = s[tx][ty + i * 8];
        __nv_bfloat16 h = __float2bfloat16_rn(v);
        Thi[(size_t)n * K + k0 + tx] = h;
        Tlo[(size_t)n * K + k0 + tx] = __float2bfloat16_rn(v - __bfloat162float(h));
    }
}

// ---------------------------------------------------------------------------
// mma.sync split-bf16 GEMM (passing since R3).
// ---------------------------------------------------------------------------
#define STAGE_BYTES  32768
#define TILE_BYTES   8192
#define GEMM_SMEM_BYTES (2 * STAGE_BYTES)

__global__ __launch_bounds__(256, 1)
void gemm_mma(const __nv_bfloat16* __restrict__ Ahi, const __nv_bfloat16* __restrict__ Alo,
              const __nv_bfloat16* __restrict__ Bhi, const __nv_bfloat16* __restrict__ Blo,
              float* __restrict__ C, int M, int N, int K)
{
    extern __shared__ char smem[];
    const uint32_t sbase = smem_to_u32(smem);
    const int tid  = threadIdx.x;
    const int wid  = tid >> 5;
    const int lane = tid & 31;
    const int br = blockIdx.y * 128;
    const int bc = blockIdx.x * 128;
    const int wr = wid & 3;
    const int wc = wid >> 2;

    const int nchunks = K >> 5;

    int r0u = (2 * tid) >> 2, u0 = (2 * tid) & 3;
    int r1u = (2 * tid + 1) >> 2, u1 = (2 * tid + 1) & 3;
    uint32_t so0 = (uint32_t)(r0u * 64 + (u0 ^ ((r0u >> 1) & 3)) * 16);
    uint32_t so1 = (uint32_t)(r1u * 64 + (u1 ^ ((r1u >> 1) & 3)) * 16);

    float acc[2][8][4];
#pragma unroll
    for (int i = 0; i < 2; i++)
#pragma unroll
        for (int j = 0; j < 8; j++)
#pragma unroll
            for (int q = 0; q < 4; q++) acc[i][j][q] = 0.f;

    const int arow0 = wr * 32 + (lane & 15);
    const int arow1 = arow0 + 16;
    const int khalf = lane >> 4;

    auto issue_loads = [&](int c, int stage) {
        uint32_t sb = sbase + stage * STAGE_BYTES;
        const __nv_bfloat16* pAh = Ahi + (size_t)br * K + c * 32;
        const __nv_bfloat16* pAl = Alo + (size_t)br * K + c * 32;
        const __nv_bfloat16* pBh = Bhi + (size_t)bc * K + c * 32;
        const __nv_bfloat16* pBl = Blo + (size_t)bc * K + c * 32;
        size_t g0 = (size_t)r0u * K + u0 * 8;
        size_t g1 = (size_t)r1u * K + u1 * 8;
        cpasync16(sb + so0,                  pAh + g0);
        cpasync16(sb + so1,                  pAh + g1);
        cpasync16(sb + TILE_BYTES + so0,     pAl + g0);
        cpasync16(sb + TILE_BYTES + so1,     pAl + g1);
        cpasync16(sb + 2*TILE_BYTES + so0,   pBh + g0);
        cpasync16(sb + 2*TILE_BYTES + so1,   pBh + g1);
        cpasync16(sb + 3*TILE_BYTES + so0,   pBl + g0);
        cpasync16(sb + 3*TILE_BYTES + so1,   pBl + g1);
    };

    issue_loads(0, 0);
    CP_COMMIT();

    for (int c = 0; c < nchunks; c++) {
        if (c + 1 < nchunks) {
            issue_loads(c + 1, (c + 1) & 1);
            CP_COMMIT();
            CP_WAIT(1);
        } else {
            CP_WAIT(0);
        }
        __syncthreads();

        uint32_t sA = sbase + (c & 1) * STAGE_BYTES;
        uint32_t sB = sA + 2 * TILE_BYTES;

#pragma unroll
        for (int kk = 0; kk < 2; kk++) {
            uint32_t ah[2][4], al[2][4];
#pragma unroll
            for (int mt = 0; mt < 2; mt++) {
                int row = (mt ? arow1 : arow0);
                int cc  = (kk * 2 + khalf) ^ ((row >> 1) & 3);
                uint32_t ad = sA + (uint32_t)(row * 64 + cc * 16);
                ldsm4(ah[mt], ad);
                ldsm4(al[mt], ad + TILE_BYTES);
            }
            uint32_t bh[4][4], bl[4][4];
#pragma unroll
            for (int ng = 0; ng < 4; ng++) {
                int row = wc * 64 + ng * 16 + (lane & 15);
                int cc  = (kk * 2 + khalf) ^ ((row >> 1) & 3);
                uint32_t bd = sB + (uint32_t)(row * 64 + cc * 16);
                ldsm4(bh[ng], bd);
                ldsm4(bl[ng], bd + TILE_BYTES);
            }
#pragma unroll
            for (int mt = 0; mt < 2; mt++)
#pragma unroll
                for (int j = 0; j < 8; j++) {
                    int ng = j >> 1, hf = j & 1;
                    mma_bf16(acc[mt][j], ah[mt], bh[ng][hf], bh[ng][2 + hf]);
                    mma_bf16(acc[mt][j], ah[mt], bl[ng][hf], bl[ng][2 + hf]);
                    mma_bf16(acc[mt][j], al[mt], bh[ng][hf], bh[ng][2 + hf]);
                }
        }
        __syncthreads();
    }

#pragma unroll
    for (int mt = 0; mt < 2; mt++) {
        int row = br + wr * 32 + mt * 16 + (lane >> 2);
#pragma unroll
        for (int j = 0; j < 8; j++) {
            int col = bc + wc * 64 + j * 8 + (lane & 3) * 2;
            *(float2*)(C + (size_t)row * N + col) =
                make_float2(acc[mt][j][0], acc[mt][j][1]);
            *(float2*)(C + (size_t)(row + 8) * N + col) =
                make_float2(acc[mt][j][2], acc[mt][j][3]);
        }
    }
}

// ---------------------------------------------------------------------------
// RoPE -> bf16 hi/lo. Q variant folds 1/sqrt(D) scale.
// ---------------------------------------------------------------------------
__global__ void rope_bf16_kernel(const float* __restrict__ buf, int nheads, int ld,
                                 const float* __restrict__ cosT,
                                 const float* __restrict__ sinT,
                                 __nv_bfloat16* __restrict__ ohi,
                                 __nv_bfloat16* __restrict__ olo,
                                 float scale, int total)
{
    int idx = blockIdx.x * blockDim.x + threadIdx.x;
    if (idx >= total) return;
    int d2 = idx & 31;
    int h  = (idx >> 5) % nheads;
    int bs = idx / (32 * nheads);
    int s  = bs & (S_ - 1);
    int d  = d2 * 2;
    const float* p = buf + (size_t)bs * ld + h * D_;
    float x1a = p[d],      x1b = p[d + 1];
    float x2a = p[d + 64], x2b = p[d + 65];
    float ca = cosT[s * D_ + d], cb = cosT[s * D_ + d + 1];
    float sa = sinT[s * D_ + d], sb = sinT[s * D_ + d + 1];
    float o1a = (x1a * ca - x2a * sa) * scale;
    float o1b = (x1b * cb - x2b * sb) * scale;
    float o2a = (x2a * ca + x1a * sa) * scale;
    float o2b = (x2b * cb + x1b * sb) * scale;
    uint32_t h1, l1, h2, l2;
    split2pack(o1a, o1b, h1, l1);
    split2pack(o2a, o2b, h2, l2);
    size_t ob = (size_t)bs * (nheads * D_) + h * D_;
    *(uint32_t*)(ohi + ob + d)      = h1;
    *(uint32_t*)(olo + ob + d)      = l1;
    *(uint32_t*)(ohi + ob + d + 64) = h2;
    *(uint32_t*)(olo + ob + d + 64) = l2;
}

// V split: g_kv cols [512,1024) -> vhi/vlo [4096][512]
__global__ void vsplit_kernel(const float* __restrict__ kv,
                              __nv_bfloat16* __restrict__ vhi,
                              __nv_bfloat16* __restrict__ vlo)
{
    int idx = blockIdx.x * blockDim.x + threadIdx.x;   // 4096*64
    int u8 = idx & 63;
    int r  = idx >> 6;
    const float* src = kv + (size_t)r * 1024 + 512 + u8 * 8;
    union { __nv_bfloat16 b[8]; uint4 u; } uh, ul;
#pragma unroll
    for (int q = 0; q < 2; q++) {
        float4 v = *(const float4*)(src + q * 4);
        float f[4] = {v.x, v.y, v.z, v.w};
#pragma unroll
        for (int i = 0; i < 4; i++) {
            __nv_bfloat16 hh = __float2bfloat16_rn(f[i]);
            uh.b[q * 4 + i] = hh;
            ul.b[q * 4 + i] = __float2bfloat16_rn(f[i] - __bfloat162float(hh));
        }
    }
    *(uint4*)(vhi + (size_t)r * 512 + u8 * 8) = uh.u;
    *(uint4*)(vlo + (size_t)r * 512 + u8 * 8) = ul.u;
}

// ---------------------------------------------------------------------------
// Tensor-core flash attention, split-bf16 for QK and PV.
// 128 q/CTA, 64-key chunks, 8 warps (m16 each), 2-stage cp.async K/V.
// smem rows: 256B (128 bf16), 16B unit swizzle u ^= (r&7).
// ---------------------------------------------------------------------------
#define A_SQH 0
#define A_SQL 32768
#define A_SKV 65536
#define A_STAGE 65536
#define ATT_SMEM_BYTES (65536 + 2*65536)   // 196608

__global__ __launch_bounds__(256, 1)
void attn_tc(const __nv_bfloat16* __restrict__ qhi, const __nv_bfloat16* __restrict__ qlo,
             const __nv_bfloat16* __restrict__ khi, const __nv_bfloat16* __restrict__ klo,
             const __nv_bfloat16* __restrict__ vhi, const __nv_bfloat16* __restrict__ vlo,
             float* __restrict__ O, const int* __restrict__ seqlen)
{
    extern __shared__ char smem[];
    const uint32_t sb = smem_to_u32(smem);
    const int tid  = threadIdx.x;
    const int wid  = tid >> 5;
    const int lane = tid & 31;
    const int bh = blockIdx.x;                 // 0..31
    const int qt = 15 - blockIdx.y;            // heavy tiles first
    const int b   = bh >> 4;
    const int h   = bh & 15;
    const int kvh = h >> 2;
    const int q0  = qt * 128;
    const int len = seqlen[b];

    // ---- load Q tile (hi/lo), 128 rows x 16 units each ----
    {
        const __nv_bfloat16* qh = qhi + (size_t)(b * S_ + q0) * (NH_*D_) + h * D_;
        const __nv_bfloat16* ql = qlo + (size_t)(b * S_ + q0) * (NH_*D_) + h * D_;
#pragma unroll
        for (int i = 0; i < 8; i++) {
            int g = i * 256 + tid;
            int r = g >> 4, u = g & 15;
            uint32_t so = (uint32_t)(r * 256 + ((u ^ (r & 7)) * 16));
            size_t go = (size_t)r * (NH_*D_) + u * 8;
            cpasync16(sb + A_SQH + so, qh + go);
            cpasync16(sb + A_SQL + so, ql + go);
        }
    }

    const int e  = min(q0 + 128, len);
    const int nt = (e + 63) >> 6;

    auto load_kv = [&](int t, int stage) {
        uint32_t st = sb + A_SKV + stage * A_STAGE;
        size_t base = (size_t)(b * S_ + t * 64) * (NKV_*D_) + kvh * D_;
#pragma unroll
        for (int i = 0; i < 4; i++) {
            int g = i * 256 + tid;
            int r = g >> 4, u = g & 15;
            uint32_t so = (uint32_t)(r * 256 + ((u ^ (r & 7)) * 16));
            size_t go = base + (size_t)r * (NKV_*D_) + u * 8;
            cpasync16(st + so,         khi + go);
            cpasync16(st + 16384 + so, klo + go);
            cpasync16(st + 32768 + so, vhi + go);
            cpasync16(st + 49152 + so, vlo + go);
        }
    };

    load_kv(0, 0);
    CP_COMMIT();

    float out[16][4];
#pragma unroll
    for (int j = 0; j < 16; j++)
#pragma unroll
        for (int q = 0; q < 4; q++) out[j][q] = 0.f;
    float m0 = -1e30f, m1 = -1e30f, l0 = 0.f, l1 = 0.f;

    const int wrow = q0 + wid * 16;            // warp's first q row (global)

    for (int t = 0; t < nt; t++) {
        if (t + 1 < nt) { load_kv(t + 1, (t + 1) & 1); CP_COMMIT(); CP_WAIT(1); }
        else            { CP_WAIT(0); }
        __syncthreads();

        const int k0 = t * 64;
        if (k0 <= wrow + 15) {                 // warp has at least one unmasked row
            uint32_t sK = sb + A_SKV + (t & 1) * A_STAGE;
            uint32_t sV = sK + 32768;

            // ---- scores S = Q K^T (m16 x 64) ----
            float s[8][4];
#pragma unroll
            for (int j = 0; j < 8; j++)
#pragma unroll
                for (int q = 0; q < 4; q++) s[j][q] = 0.f;

#pragma unroll
            for (int kk = 0; kk < 8; kk++) {
                int ar = wid * 16 + (lane & 15);
                int au = 2 * kk + (lane >> 4);
                uint32_t aso = (uint32_t)(ar * 256 + ((au ^ (ar & 7)) * 16));
                uint32_t ah[4], al[4];
                ldsm4(ah, sb + A_SQH + aso);
                ldsm4(al, sb + A_SQL + aso);
#pragma unroll
                for (int ng = 0; ng < 4; ng++) {
                    int br = ng * 16 + (lane & 15);
                    uint32_t bso = (uint32_t)(br * 256 + ((au ^ (br & 7)) * 16));
                    uint32_t bhf[4], blf[4];
                    ldsm4(bhf, sK + bso);
                    ldsm4(blf, sK + 16384 + bso);
#pragma unroll
                    for (int hf = 0; hf < 2; hf++) {
                        int j = 2 * ng + hf;
                        mma_bf16(s[j], ah, bhf[hf], bhf[2 + hf]);
                        mma_bf16(s[j], ah, blf[hf], blf[2 + hf]);
                        mma_bf16(s[j], al, bhf[hf], bhf[2 + hf]);
                    }
                }
            }

            // ---- mask ----
            const int qr0 = wrow + (lane >> 2);
            bool fullvalid = (k0 + 63 <= wrow) && (k0 + 63 < len);
            if (!fullvalid) {
#pragma unroll
                for (int j = 0; j < 8; j++) {
                    int kgb = k0 + j * 8 + (lane & 3) * 2;
#pragma unroll
                    for (int q = 0; q < 4; q++) {
                        int kg = kgb + (q & 1);
                        int qg = qr0 + ((q >> 1) << 3);
                        if (kg > qg || kg >= len) s[j][q] = -1e30f;
                    }
                }
            }

            // ---- online softmax ----
            float mx0 = -1e30f, mx1 = -1e30f;
#pragma unroll
            for (int j = 0; j < 8; j++) {
                mx0 = fmaxf(mx0, fmaxf(s[j][0], s[j][1]));
                mx1 = fmaxf(mx1, fmaxf(s[j][2], s[j][3]));
            }
#pragma unroll
            for (int off = 1; off <= 2; off <<= 1) {
                mx0 = fmaxf(mx0, __shfl_xor_sync(0xffffffffu, mx0, off));
                mx1 = fmaxf(mx1, __shfl_xor_sync(0xffffffffu, mx1, off));
            }
            float nm0 = fmaxf(m0, mx0), nm1 = fmaxf(m1, mx1);
            float sc0 = __expf(m0 - nm0), sc1 = __expf(m1 - nm1);
            m0 = nm0; m1 = nm1;
            float sum0 = 0.f, sum1 = 0.f;
#pragma unroll
            for (int j = 0; j < 8; j++) {
                s[j][0] = __expf(s[j][0] - nm0);
                s[j][1] = __expf(s[j][1] - nm0);
                s[j][2] = __expf(s[j][2] - nm1);
                s[j][3] = __expf(s[j][3] - nm1);
                sum0 += s[j][0] + s[j][1];
                sum1 += s[j][2] + s[j][3];
            }
#pragma unroll
            for (int off = 1; off <= 2; off <<= 1) {
                sum0 += __shfl_xor_sync(0xffffffffu, sum0, off);
                sum1 += __shfl_xor_sync(0xffffffffu, sum1, off);
            }
            l0 = l0 * sc0 + sum0;
            l1 = l1 * sc1 + sum1;
#pragma unroll
            for (int j = 0; j < 16; j++) {
                out[j][0] *= sc0; out[j][1] *= sc0;
                out[j][2] *= sc1; out[j][3] *= sc1;
            }

            // ---- PV: out += P V ----
#pragma unroll
            for (int jk = 0; jk < 4; jk++) {
                uint32_t ph[4], pl[4];
                split2pack(s[2*jk][0],   s[2*jk][1],   ph[0], pl[0]);
                split2pack(s[2*jk][2],   s[2*jk][3],   ph[1], pl[1]);
                split2pack(s[2*jk+1][0], s[2*jk+1][1], ph[2], pl[2]);
                split2pack(s[2*jk+1][2], s[2*jk+1][3], ph[3], pl[3]);
#pragma unroll
                for (int gn = 0; gn < 8; gn++) {
                    int vr = jk * 16 + (lane & 15);
                    int vu = 2 * gn + (lane >> 4);
                    uint32_t vso = (uint32_t)(vr * 256 + ((vu ^ (vr & 7)) * 16));
                    uint32_t vh4[4], vl4[4];
                    ldsm4t(vh4, sV + vso);
                    ldsm4t(vl4, sV + 16384 + vso);
#pragma unroll
                    for (int hf = 0; hf < 2; hf++) {
                        int jn = 2 * gn + hf;
                        mma_bf16(out[jn], ph, vh4[2*hf], vh4[2*hf + 1]);
                        mma_bf16(out[jn], pl, vh4[2*hf], vh4[2*hf + 1]);
                        mma_bf16(out[jn], ph, vl4[2*hf], vl4[2*hf + 1]);
                    }
                }
            }
        }
        __syncthreads();
    }

    // ---- epilogue ----
    float i0 = 1.0f / l0, i1 = 1.0f / l1;
    int orow = b * S_ + wrow + (lane >> 2);
    float* ob = O + (size_t)orow * (NH_*D_) + h * D_;
#pragma unroll
    for (int jn = 0; jn < 16; jn++) {
        int col = jn * 8 + (lane & 3) * 2;
        *(float2*)(ob + col) = make_float2(out[jn][0] * i0, out[jn][1] * i0);
        *(float2*)(ob + 8 * (NH_*D_) + col) = make_float2(out[jn][2] * i1, out[jn][3] * i1);
    }
}

// ---------------------------------------------------------------------------
// Launch
// ---------------------------------------------------------------------------
extern "C" void kernel_launch(void* const* d_in, const int* in_sizes, int n_in,
                              void* d_out, int out_size)
{
    const float* x    = (const float*)d_in[0];
    const int*   seq  = (const int*)  d_in[1];
    const float* fcos = (const float*)d_in[2];
    const float* fsin = (const float*)d_in[3];
    const float* Wq   = (const float*)d_in[4];
    const float* Wkv  = (const float*)d_in[5];
    const float* Wo   = (const float*)d_in[6];
    float* out = (float*)d_out;

    float *qp, *kvp, *ap;
    cudaGetSymbolAddress((void**)&qp,  g_q);
    cudaGetSymbolAddress((void**)&kvp, g_kv);
    cudaGetSymbolAddress((void**)&ap,  g_att);
    __nv_bfloat16 *xhi, *xlo, *ahi, *alo, *wqh, *wql, *wkh, *wkl, *woh, *wol;
    __nv_bfloat16 *qhi, *qlo, *khi, *klo, *vhi, *vlo;
    cudaGetSymbolAddress((void**)&xhi, g_xhi);
    cudaGetSymbolAddress((void**)&xlo, g_xlo);
    cudaGetSymbolAddress((void**)&ahi, g_ahi);
    cudaGetSymbolAddress((void**)&alo, g_alo);
    cudaGetSymbolAddress((void**)&wqh, g_wqh);
    cudaGetSymbolAddress((void**)&wql, g_wql);
    cudaGetSymbolAddress((void**)&wkh, g_wkh);
    cudaGetSymbolAddress((void**)&wkl, g_wkl);
    cudaGetSymbolAddress((void**)&woh, g_woh);
    cudaGetSymbolAddress((void**)&wol, g_wol);
    cudaGetSymbolAddress((void**)&qhi, g_qhi);
    cudaGetSymbolAddress((void**)&qlo, g_qlo);
    cudaGetSymbolAddress((void**)&khi, g_khi);
    cudaGetSymbolAddress((void**)&klo, g_klo);
    cudaGetSymbolAddress((void**)&vhi, g_vhi);
    cudaGetSymbolAddress((void**)&vlo, g_vlo);

    cudaFuncSetAttribute(gemm_mma, cudaFuncAttributeMaxDynamicSharedMemorySize, GEMM_SMEM_BYTES);
    cudaFuncSetAttribute(attn_tc,  cudaFuncAttributeMaxDynamicSharedMemorySize, ATT_SMEM_BYTES);

    dim3 blk(256);

    // 0) precision-split preprocessing
    {
        int n8 = MROWS * H_ / 8;
        split_kernel<<<(n8 + 255) / 256, 256>>>(x, xhi, xlo, n8);
        dim3 tb(32, 8);
        splitT_kernel<<<dim3((NH_*D_)/32,    H_/32), tb>>>(Wq,  wqh, wql, H_, NH_*D_);
        splitT_kernel<<<dim3((2*NKV_*D_)/32, H_/32), tb>>>(Wkv, wkh, wkl, H_, 2*NKV_*D_);
        splitT_kernel<<<dim3(H_/32,          H_/32), tb>>>(Wo,  woh, wol, H_, H_);
    }

    // 1) projections (mma.sync split-bf16)
    gemm_mma<<<dim3(16, 32), blk, GEMM_SMEM_BYTES>>>(xhi, xlo, wqh, wql, qp,  MROWS, NH_*D_,    H_);
    gemm_mma<<<dim3(8,  32), blk, GEMM_SMEM_BYTES>>>(xhi, xlo, wkh, wkl, kvp, MROWS, 2*NKV_*D_, H_);

    // 2) RoPE -> bf16 hi/lo (Q folds softmax scale); V split
    {
        int tq = MROWS * NH_ * 32;
        int tk = MROWS * NKV_ * 32;
        rope_bf16_kernel<<<(tq + 255) / 256, 256>>>(qp,  NH_,  NH_ * D_,      fcos, fsin, qhi, qlo, QSCALE, tq);
        rope_bf16_kernel<<<(tk + 255) / 256, 256>>>(kvp, NKV_, 2 * NKV_ * D_, fcos, fsin, khi, klo, 1.0f,   tk);
        int tv = MROWS * 64;
        vsplit_kernel<<<(tv + 255) / 256, 256>>>(kvp, vhi, vlo);
    }

    // 3) attention (tensor-core, split-bf16)
    attn_tc<<<dim3(32, 16), blk, ATT_SMEM_BYTES>>>(qhi, qlo, khi, klo, vhi, vlo, ap, seq);

    // 4) output projection
    {
        int n8 = MROWS * H_ / 8;
        split_kernel<<<(n8 + 255) / 256, 256>>>(ap, ahi, alo, n8);
    }
    gemm_mma<<<dim3(16, 32), blk, GEMM_SMEM_BYTES>>>(ahi, alo, woh, wol, out, MROWS, H_, H_);
}

// round 6
// speedup vs baseline: 2.2867x; 1.0428x over previous
#include <cuda_runtime.h>
#include <cuda_bf16.h>
#include <cstdint>
#include <cstddef>

// Problem constants
#define B_   2
#define S_   2048
#define H_   2048
#define NH_  16
#define NKV_ 4
#define D_   128
#define MROWS (B_*S_)          // 4096
#define NQKV 3072              // 2048 q | 512 k | 512 v
#define QSCALE 0.08838834764831845f

// ---------------------------------------------------------------------------
// PTX helpers (sm_100-safe: mma.sync / ldmatrix / cp.async only)
// ---------------------------------------------------------------------------
__device__ __forceinline__ uint32_t smem_to_u32(const void* p) {
    uint32_t a;
    asm("{ .reg .u64 t; cvta.to.shared.u64 t, %1; cvt.u32.u64 %0, t; }" : "=r"(a) : "l"(p));
    return a;
}
__device__ __forceinline__ void ldsm4(uint32_t* r, uint32_t addr) {
    asm volatile("ldmatrix.sync.aligned.m8n8.x4.shared.b16 {%0,%1,%2,%3}, [%4];"
        : "=r"(r[0]), "=r"(r[1]), "=r"(r[2]), "=r"(r[3]) : "r"(addr));
}
__device__ __forceinline__ void ldsm4t(uint32_t* r, uint32_t addr) {
    asm volatile("ldmatrix.sync.aligned.m8n8.x4.trans.shared.b16 {%0,%1,%2,%3}, [%4];"
        : "=r"(r[0]), "=r"(r[1]), "=r"(r[2]), "=r"(r[3]) : "r"(addr));
}
__device__ __forceinline__ void mma_bf16(float* d, const uint32_t* a, uint32_t b0, uint32_t b1) {
    asm volatile("mma.sync.aligned.m16n8k16.row.col.f32.bf16.bf16.f32 "
        "{%0,%1,%2,%3}, {%4,%5,%6,%7}, {%8,%9}, {%0,%1,%2,%3};"
        : "+f"(d[0]), "+f"(d[1]), "+f"(d[2]), "+f"(d[3])
        : "r"(a[0]), "r"(a[1]), "r"(a[2]), "r"(a[3]), "r"(b0), "r"(b1));
}
__device__ __forceinline__ void cpasync16(uint32_t saddr, const void* g) {
    asm volatile("cp.async.cg.shared.global [%0], [%1], 16;" :: "r"(saddr), "l"(g));
}
#define CP_COMMIT() asm volatile("cp.async.commit_group;" ::: "memory")
#define CP_WAIT(n)  asm volatile("cp.async.wait_group %0;" :: "n"(n) : "memory")

__device__ __forceinline__ void split2pack(float a, float b, uint32_t& hi, uint32_t& lo) {
    __nv_bfloat16 ah = __float2bfloat16_rn(a);
    __nv_bfloat16 bh = __float2bfloat16_rn(b);
    __nv_bfloat16 al = __float2bfloat16_rn(a - __bfloat162float(ah));
    __nv_bfloat16 bl = __float2bfloat16_rn(b - __bfloat162float(bh));
    hi = (uint32_t)(*(uint16_t*)&ah) | ((uint32_t)(*(uint16_t*)&bh) << 16);
    lo = (uint32_t)(*(uint16_t*)&al) | ((uint32_t)(*(uint16_t*)&bl) << 16);
}

// ---------------------------------------------------------------------------
// Scratch (device globals)
// ---------------------------------------------------------------------------
__device__ float g_qkv[(size_t)MROWS * NQKV];        // fp32 q|k|v projections

__device__ __nv_bfloat16 g_xhi[(size_t)MROWS * H_];
__device__ __nv_bfloat16 g_xlo[(size_t)MROWS * H_];
__device__ __nv_bfloat16 g_ahi[(size_t)MROWS * H_];  // attention out (bf16 split)
__device__ __nv_bfloat16 g_alo[(size_t)MROWS * H_];
__device__ __nv_bfloat16 g_wh [(size_t)NQKV * H_];   // [3072,2048] Wq|Wkv transposed
__device__ __nv_bfloat16 g_wl [(size_t)NQKV * H_];
__device__ __nv_bfloat16 g_woh[(size_t)H_ * H_];
__device__ __nv_bfloat16 g_wol[(size_t)H_ * H_];
// attention operands (bf16 hi/lo)
__device__ __nv_bfloat16 g_qhi[(size_t)MROWS * (NH_*D_)];
__device__ __nv_bfloat16 g_qlo[(size_t)MROWS * (NH_*D_)];
__device__ __nv_bfloat16 g_khi[(size_t)MROWS * (NKV_*D_)];
__device__ __nv_bfloat16 g_klo[(size_t)MROWS * (NKV_*D_)];
__device__ __nv_bfloat16 g_vhi[(size_t)MROWS * (NKV_*D_)];
__device__ __nv_bfloat16 g_vlo[(size_t)MROWS * (NKV_*D_)];

// ---------------------------------------------------------------------------
// split fp32 -> bf16 hi/lo (row-major, same layout). 8 elems/thread.
// ---------------------------------------------------------------------------
__global__ void split_kernel(const float* __restrict__ in,
                             __nv_bfloat16* __restrict__ hi,
                             __nv_bfloat16* __restrict__ lo, int n8)
{
    int idx = blockIdx.x * blockDim.x + threadIdx.x;
    if (idx >= n8) return;
    union { __nv_bfloat16 b[8]; uint4 u; } uh, ul;
    const float4* in4 = (const float4*)in;
#pragma unroll
    for (int q = 0; q < 2; q++) {
        float4 v = in4[idx * 2 + q];
        float f[4] = {v.x, v.y, v.z, v.w};
#pragma unroll
        for (int i = 0; i < 4; i++) {
            __nv_bfloat16 h = __float2bfloat16_rn(f[i]);
            uh.b[q * 4 + i] = h;
            ul.b[q * 4 + i] = __float2bfloat16_rn(f[i] - __bfloat162float(h));
        }
    }
    ((uint4*)hi)[idx] = uh.u;
    ((uint4*)lo)[idx] = ul.u;
}

// ---------------------------------------------------------------------------
// split + transpose: W[K,N] fp32 -> Thi/Tlo[N,K] bf16. 32x32 smem tiles.
// ---------------------------------------------------------------------------
__global__ void splitT_kernel(const float* __restrict__ W,
                              __nv_bfloat16* __restrict__ Thi,
                              __nv_bfloat16* __restrict__ Tlo, int K, int N)
{
    __shared__ float s[32][33];
    int tx = threadIdx.x, ty = threadIdx.y;           // (32, 8)
    int n0 = blockIdx.x * 32, k0 = blockIdx.y * 32;
#pragma unroll
    for (int i = 0; i < 4; i++) {
        int k = k0 + ty + i * 8;
        s[ty + i * 8][tx] = W[(size_t)k * N + n0 + tx];
    }
    __syncthreads();
#pragma unroll
    for (int i = 0; i < 4; i++) {
        int n = n0 + ty + i * 8;
        float v = s[tx][ty + i * 8];
        __nv_bfloat16 h = __float2bfloat16_rn(v);
        Thi[(size_t)n * K + k0 + tx] = h;
        Tlo[(size_t)n * K + k0 + tx] = __float2bfloat16_rn(v - __bfloat162float(h));
    }
}

// ---------------------------------------------------------------------------
// mma.sync split-bf16 GEMM: 4-stage cp.async, ONE barrier per chunk.
// 128x128 CTA tile, BK=32, 8 warps (4x2 -> 32x64 warp tiles).
// ---------------------------------------------------------------------------
#define STAGE_BYTES  32768
#define TILE_BYTES   8192
#define NSTAGE 4
#define GEMM_SMEM_BYTES (NSTAGE * STAGE_BYTES)   // 131072

__global__ __launch_bounds__(256, 1)
void gemm_mma(const __nv_bfloat16* __restrict__ Ahi, const __nv_bfloat16* __restrict__ Alo,
              const __nv_bfloat16* __restrict__ Bhi, const __nv_bfloat16* __restrict__ Blo,
              float* __restrict__ C, int M, int N, int K)
{
    extern __shared__ char smem[];
    const uint32_t sbase = smem_to_u32(smem);
    const int tid  = threadIdx.x;
    const int wid  = tid >> 5;
    const int lane = tid & 31;
    const int br = blockIdx.y * 128;
    const int bc = blockIdx.x * 128;
    const int wr = wid & 3;
    const int wc = wid >> 2;

    const int nchunks = K >> 5;

    int r0u = (2 * tid) >> 2, u0 = (2 * tid) & 3;
    int r1u = (2 * tid + 1) >> 2, u1 = (2 * tid + 1) & 3;
    uint32_t so0 = (uint32_t)(r0u * 64 + (u0 ^ ((r0u >> 1) & 3)) * 16);
    uint32_t so1 = (uint32_t)(r1u * 64 + (u1 ^ ((r1u >> 1) & 3)) * 16);

    float acc[2][8][4];
#pragma unroll
    for (int i = 0; i < 2; i++)
#pragma unroll
        for (int j = 0; j < 8; j++)
#pragma unroll
            for (int q = 0; q < 4; q++) acc[i][j][q] = 0.f;

    const int arow0 = wr * 32 + (lane & 15);
    const int arow1 = arow0 + 16;
    const int khalf = lane >> 4;

    auto issue_loads = [&](int c, int stage) {
        uint32_t sb = sbase + stage * STAGE_BYTES;
        const __nv_bfloat16* pAh = Ahi + (size_t)br * K + c * 32;
        const __nv_bfloat16* pAl = Alo + (size_t)br * K + c * 32;
        const __nv_bfloat16* pBh = Bhi + (size_t)bc * K + c * 32;
        const __nv_bfloat16* pBl = Blo + (size_t)bc * K + c * 32;
        size_t g0 = (size_t)r0u * K + u0 * 8;
        size_t g1 = (size_t)r1u * K + u1 * 8;
        cpasync16(sb + so0,                  pAh + g0);
        cpasync16(sb + so1,                  pAh + g1);
        cpasync16(sb + TILE_BYTES + so0,     pAl + g0);
        cpasync16(sb + TILE_BYTES + so1,     pAl + g1);
        cpasync16(sb + 2*TILE_BYTES + so0,   pBh + g0);
        cpasync16(sb + 2*TILE_BYTES + so1,   pBh + g1);
        cpasync16(sb + 3*TILE_BYTES + so0,   pBl + g0);
        cpasync16(sb + 3*TILE_BYTES + so1,   pBl + g1);
    };

    // prologue: chunks 0..2 into stages 0..2 (groups 0..2)
#pragma unroll
    for (int c = 0; c < 3; c++) {
        if (c < nchunks) issue_loads(c, c);
        CP_COMMIT();
    }

    for (int c = 0; c < nchunks; c++) {
        CP_WAIT(2);                 // group c complete
        __syncthreads();            // stage (c-1)&3 fully drained by all warps
        if (c + 3 < nchunks) issue_loads(c + 3, (c + 3) & 3);
        CP_COMMIT();                // unconditional: keeps group index == chunk index

        uint32_t sA = sbase + (c & 3) * STAGE_BYTES;
        uint32_t sB = sA + 2 * TILE_BYTES;

#pragma unroll
        for (int kk = 0; kk < 2; kk++) {
            uint32_t ah[2][4], al[2][4];
#pragma unroll
            for (int mt = 0; mt < 2; mt++) {
                int row = (mt ? arow1 : arow0);
                int cc  = (kk * 2 + khalf) ^ ((row >> 1) & 3);
                uint32_t ad = sA + (uint32_t)(row * 64 + cc * 16);
                ldsm4(ah[mt], ad);
                ldsm4(al[mt], ad + TILE_BYTES);
            }
            uint32_t bh[4][4], bl[4][4];
#pragma unroll
            for (int ng = 0; ng < 4; ng++) {
                int row = wc * 64 + ng * 16 + (lane & 15);
                int cc  = (kk * 2 + khalf) ^ ((row >> 1) & 3);
                uint32_t bd = sB + (uint32_t)(row * 64 + cc * 16);
                ldsm4(bh[ng], bd);
                ldsm4(bl[ng], bd + TILE_BYTES);
            }
#pragma unroll
            for (int mt = 0; mt < 2; mt++)
#pragma unroll
                for (int j = 0; j < 8; j++) {
                    int ng = j >> 1, hf = j & 1;
                    mma_bf16(acc[mt][j], ah[mt], bh[ng][hf], bh[ng][2 + hf]);
                    mma_bf16(acc[mt][j], ah[mt], bl[ng][hf], bl[ng][2 + hf]);
                    mma_bf16(acc[mt][j], al[mt], bh[ng][hf], bh[ng][2 + hf]);
                }
        }
    }

#pragma unroll
    for (int mt = 0; mt < 2; mt++) {
        int row = br + wr * 32 + mt * 16 + (lane >> 2);
#pragma unroll
        for (int j = 0; j < 8; j++) {
            int col = bc + wc * 64 + j * 8 + (lane & 3) * 2;
            *(float2*)(C + (size_t)row * N + col) =
                make_float2(acc[mt][j][0], acc[mt][j][1]);
            *(float2*)(C + (size_t)(row + 8) * N + col) =
                make_float2(acc[mt][j][2], acc[mt][j][3]);
        }
    }
}

// ---------------------------------------------------------------------------
// RoPE -> bf16 hi/lo. Q variant folds 1/sqrt(D) scale.
// ---------------------------------------------------------------------------
__global__ void rope_bf16_kernel(const float* __restrict__ buf, int nheads, int ld,
                                 const float* __restrict__ cosT,
                                 const float* __restrict__ sinT,
                                 __nv_bfloat16* __restrict__ ohi,
                                 __nv_bfloat16* __restrict__ olo,
                                 float scale, int total)
{
    int idx = blockIdx.x * blockDim.x + threadIdx.x;
    if (idx >= total) return;
    int d2 = idx & 31;
    int h  = (idx >> 5) % nheads;
    int bs = idx / (32 * nheads);
    int s  = bs & (S_ - 1);
    int d  = d2 * 2;
    const float* p = buf + (size_t)bs * ld + h * D_;
    float x1a = p[d],      x1b = p[d + 1];
    float x2a = p[d + 64], x2b = p[d + 65];
    float ca = cosT[s * D_ + d], cb = cosT[s * D_ + d + 1];
    float sa = sinT[s * D_ + d], sb = sinT[s * D_ + d + 1];
    float o1a = (x1a * ca - x2a * sa) * scale;
    float o1b = (x1b * cb - x2b * sb) * scale;
    float o2a = (x2a * ca + x1a * sa) * scale;
    float o2b = (x2b * cb + x1b * sb) * scale;
    uint32_t h1, l1, h2, l2;
    split2pack(o1a, o1b, h1, l1);
    split2pack(o2a, o2b, h2, l2);
    size_t ob = (size_t)bs * (nheads * D_) + h * D_;
    *(uint32_t*)(ohi + ob + d)      = h1;
    *(uint32_t*)(olo + ob + d)      = l1;
    *(uint32_t*)(ohi + ob + d + 64) = h2;
    *(uint32_t*)(olo + ob + d + 64) = l2;
}

// V split: g_qkv cols [2560,3072) -> vhi/vlo [4096][512]
__global__ void vsplit_kernel(const float* __restrict__ qkv,
                              __nv_bfloat16* __restrict__ vhi,
                              __nv_bfloat16* __restrict__ vlo)
{
    int idx = blockIdx.x * blockDim.x + threadIdx.x;   // 4096*64
    int u8 = idx & 63;
    int r  = idx >> 6;
    const float* src = qkv + (size_t)r * NQKV + 2560 + u8 * 8;
    union { __nv_bfloat16 b[8]; uint4 u; } uh, ul;
#pragma unroll
    for (int q = 0; q < 2; q++) {
        float4 v = *(const float4*)(src + q * 4);
        float f[4] = {v.x, v.y, v.z, v.w};
#pragma unroll
        for (int i = 0; i < 4; i++) {
            __nv_bfloat16 hh = __float2bfloat16_rn(f[i]);
            uh.b[q * 4 + i] = hh;
            ul.b[q * 4 + i] = __float2bfloat16_rn(f[i] - __bfloat162float(hh));
        }
    }
    *(uint4*)(vhi + (size_t)r * 512 + u8 * 8) = uh.u;
    *(uint4*)(vlo + (size_t)r * 512 + u8 * 8) = ul.u;
}

// ---------------------------------------------------------------------------
// Tensor-core flash attention, split-bf16 for QK and PV.
// Epilogue writes bf16 hi/lo directly (feeds Wo GEMM; no fp32 round trip).
// ---------------------------------------------------------------------------
#define A_SQH 0
#define A_SQL 32768
#define A_SKV 65536
#define A_STAGE 65536
#define ATT_SMEM_BYTES (65536 + 2*65536)   // 196608

__global__ __launch_bounds__(256, 1)
void attn_tc(const __nv_bfloat16* __restrict__ qhi, const __nv_bfloat16* __restrict__ qlo,
             const __nv_bfloat16* __restrict__ khi, const __nv_bfloat16* __restrict__ klo,
             const __nv_bfloat16* __restrict__ vhi, const __nv_bfloat16* __restrict__ vlo,
             __nv_bfloat16* __restrict__ Ohi, __nv_bfloat16* __restrict__ Olo,
             const int* __restrict__ seqlen)
{
    extern __shared__ char smem[];
    const uint32_t sb = smem_to_u32(smem);
    const int tid  = threadIdx.x;
    const int wid  = tid >> 5;
    const int lane = tid & 31;
    const int bh = blockIdx.x;                 // 0..31
    const int qt = 15 - blockIdx.y;            // heavy tiles first
    const int b   = bh >> 4;
    const int h   = bh & 15;
    const int kvh = h >> 2;
    const int q0  = qt * 128;
    const int len = seqlen[b];

    // ---- load Q tile (hi/lo), 128 rows x 16 units each ----
    {
        const __nv_bfloat16* qh = qhi + (size_t)(b * S_ + q0) * (NH_*D_) + h * D_;
        const __nv_bfloat16* ql = qlo + (size_t)(b * S_ + q0) * (NH_*D_) + h * D_;
#pragma unroll
        for (int i = 0; i < 8; i++) {
            int g = i * 256 + tid;
            int r = g >> 4, u = g & 15;
            uint32_t so = (uint32_t)(r * 256 + ((u ^ (r & 7)) * 16));
            size_t go = (size_t)r * (NH_*D_) + u * 8;
            cpasync16(sb + A_SQH + so, qh + go);
            cpasync16(sb + A_SQL + so, ql + go);
        }
    }

    const int e  = min(q0 + 128, len);
    const int nt = (e + 63) >> 6;

    auto load_kv = [&](int t, int stage) {
        uint32_t st = sb + A_SKV + stage * A_STAGE;
        size_t base = (size_t)(b * S_ + t * 64) * (NKV_*D_) + kvh * D_;
#pragma unroll
        for (int i = 0; i < 4; i++) {
            int g = i * 256 + tid;
            int r = g >> 4, u = g & 15;
            uint32_t so = (uint32_t)(r * 256 + ((u ^ (r & 7)) * 16));
            size_t go = base + (size_t)r * (NKV_*D_) + u * 8;
            cpasync16(st + so,         khi + go);
            cpasync16(st + 16384 + so, klo + go);
            cpasync16(st + 32768 + so, vhi + go);
            cpasync16(st + 49152 + so, vlo + go);
        }
    };

    load_kv(0, 0);
    CP_COMMIT();

    float out[16][4];
#pragma unroll
    for (int j = 0; j < 16; j++)
#pragma unroll
        for (int q = 0; q < 4; q++) out[j][q] = 0.f;
    float m0 = -1e30f, m1 = -1e30f, l0 = 0.f, l1 = 0.f;

    const int wrow = q0 + wid * 16;            // warp's first q row (global)

    for (int t = 0; t < nt; t++) {
        if (t + 1 < nt) { load_kv(t + 1, (t + 1) & 1); CP_COMMIT(); CP_WAIT(1); }
        else            { CP_WAIT(0); }
        __syncthreads();

        const int k0 = t * 64;
        if (k0 <= wrow + 15) {                 // warp has at least one unmasked row
            uint32_t sK = sb + A_SKV + (t & 1) * A_STAGE;
            uint32_t sV = sK + 32768;

            // ---- scores S = Q K^T (m16 x 64) ----
            float s[8][4];
#pragma unroll
            for (int j = 0; j < 8; j++)
#pragma unroll
                for (int q = 0; q < 4; q++) s[j][q] = 0.f;

#pragma unroll
            for (int kk = 0; kk < 8; kk++) {
                int ar = wid * 16 + (lane & 15);
                int au = 2 * kk + (lane >> 4);
                uint32_t aso = (uint32_t)(ar * 256 + ((au ^ (ar & 7)) * 16));
                uint32_t ah[4], al[4];
                ldsm4(ah, sb + A_SQH + aso);
                ldsm4(al, sb + A_SQL + aso);
#pragma unroll
                for (int ng = 0; ng < 4; ng++) {
                    int br = ng * 16 + (lane & 15);
                    uint32_t bso = (uint32_t)(br * 256 + ((au ^ (br & 7)) * 16));
                    uint32_t bhf[4], blf[4];
                    ldsm4(bhf, sK + bso);
                    ldsm4(blf, sK + 16384 + bso);
#pragma unroll
                    for (int hf = 0; hf < 2; hf++) {
                        int j = 2 * ng + hf;
                        mma_bf16(s[j], ah, bhf[hf], bhf[2 + hf]);
                        mma_bf16(s[j], ah, blf[hf], blf[2 + hf]);
                        mma_bf16(s[j], al, bhf[hf], bhf[2 + hf]);
                    }
                }
            }

            // ---- mask ----
            const int qr0 = wrow + (lane >> 2);
            bool fullvalid = (k0 + 63 <= wrow) && (k0 + 63 < len);
            if (!fullvalid) {
#pragma unroll
                for (int j = 0; j < 8; j++) {
                    int kgb = k0 + j * 8 + (lane & 3) * 2;
#pragma unroll
                    for (int q = 0; q < 4; q++) {
                        int kg = kgb + (q & 1);
                        int qg = qr0 + ((q >> 1) << 3);
                        if (kg > qg || kg >= len) s[j][q] = -1e30f;
                    }
                }
            }

            // ---- online softmax ----
            float mx0 = -1e30f, mx1 = -1e30f;
#pragma unroll
            for (int j = 0; j < 8; j++) {
                mx0 = fmaxf(mx0, fmaxf(s[j][0], s[j][1]));
                mx1 = fmaxf(mx1, fmaxf(s[j][2], s[j][3]));
            }
#pragma unroll
            for (int off = 1; off <= 2; off <<= 1) {
                mx0 = fmaxf(mx0, __shfl_xor_sync(0xffffffffu, mx0, off));
                mx1 = fmaxf(mx1, __shfl_xor_sync(0xffffffffu, mx1, off));
            }
            float nm0 = fmaxf(m0, mx0), nm1 = fmaxf(m1, mx1);
            float sc0 = __expf(m0 - nm0), sc1 = __expf(m1 - nm1);
            m0 = nm0; m1 = nm1;
            float sum0 = 0.f, sum1 = 0.f;
#pragma unroll
            for (int j = 0; j < 8; j++) {
                s[j][0] = __expf(s[j][0] - nm0);
                s[j][1] = __expf(s[j][1] - nm0);
                s[j][2] = __expf(s[j][2] - nm1);
                s[j][3] = __expf(s[j][3] - nm1);
                sum0 += s[j][0] + s[j][1];
                sum1 += s[j][2] + s[j][3];
            }
#pragma unroll
            for (int off = 1; off <= 2; off <<= 1) {
                sum0 += __shfl_xor_sync(0xffffffffu, sum0, off);
                sum1 += __shfl_xor_sync(0xffffffffu, sum1, off);
            }
            l0 = l0 * sc0 + sum0;
            l1 = l1 * sc1 + sum1;
#pragma unroll
            for (int j = 0; j < 16; j++) {
                out[j][0] *= sc0; out[j][1] *= sc0;
                out[j][2] *= sc1; out[j][3] *= sc1;
            }

            // ---- PV: out += P V ----
#pragma unroll
            for (int jk = 0; jk < 4; jk++) {
                uint32_t ph[4], pl[4];
                split2pack(s[2*jk][0],   s[2*jk][1],   ph[0], pl[0]);
                split2pack(s[2*jk][2],   s[2*jk][3],   ph[1], pl[1]);
                split2pack(s[2*jk+1][0], s[2*jk+1][1], ph[2], pl[2]);
                split2pack(s[2*jk+1][2], s[2*jk+1][3], ph[3], pl[3]);
#pragma unroll
                for (int gn = 0; gn < 8; gn++) {
                    int vr = jk * 16 + (lane & 15);
                    int vu = 2 * gn + (lane >> 4);
                    uint32_t vso = (uint32_t)(vr * 256 + ((vu ^ (vr & 7)) * 16));
                    uint32_t vh4[4], vl4[4];
                    ldsm4t(vh4, sV + vso);
                    ldsm4t(vl4, sV + 16384 + vso);
#pragma unroll
                    for (int hf = 0; hf < 2; hf++) {
                        int jn = 2 * gn + hf;
                        mma_bf16(out[jn], ph, vh4[2*hf], vh4[2*hf + 1]);
                        mma_bf16(out[jn], pl, vh4[2*hf], vh4[2*hf + 1]);
                        mma_bf16(out[jn], ph, vl4[2*hf], vl4[2*hf + 1]);
                    }
                }
            }
        }
        __syncthreads();
    }

    // ---- epilogue: normalize, split to bf16 hi/lo, store ----
    float i0 = 1.0f / l0, i1 = 1.0f / l1;
    size_t ro0 = (size_t)(b * S_ + wrow + (lane >> 2)) * (NH_*D_) + h * D_;
    size_t ro1 = ro0 + (size_t)8 * (NH_*D_);
#pragma unroll
    for (int jn = 0; jn < 16; jn++) {
        int col = jn * 8 + (lane & 3) * 2;
        uint32_t hh, ll;
        split2pack(out[jn][0] * i0, out[jn][1] * i0, hh, ll);
        *(uint32_t*)(Ohi + ro0 + col) = hh;
        *(uint32_t*)(Olo + ro0 + col) = ll;
        split2pack(out[jn][2] * i1, out[jn][3] * i1, hh, ll);
        *(uint32_t*)(Ohi + ro1 + col) = hh;
        *(uint32_t*)(Olo + ro1 + col) = ll;
    }
}

// ---------------------------------------------------------------------------
// Launch
// ---------------------------------------------------------------------------
extern "C" void kernel_launch(void* const* d_in, const int* in_sizes, int n_in,
                              void* d_out, int out_size)
{
    const float* x    = (const float*)d_in[0];
    const int*   seq  = (const int*)  d_in[1];
    const float* fcos = (const float*)d_in[2];
    const float* fsin = (const float*)d_in[3];
    const float* Wq   = (const float*)d_in[4];
    const float* Wkv  = (const float*)d_in[5];
    const float* Wo   = (const float*)d_in[6];
    float* out = (float*)d_out;

    float *qkv;
    cudaGetSymbolAddress((void**)&qkv, g_qkv);
    __nv_bfloat16 *xhi, *xlo, *ahi, *alo, *wh, *wl, *woh, *wol;
    __nv_bfloat16 *qhi, *qlo, *khi, *klo, *vhi, *vlo;
    cudaGetSymbolAddress((void**)&xhi, g_xhi);
    cudaGetSymbolAddress((void**)&xlo, g_xlo);
    cudaGetSymbolAddress((void**)&ahi, g_ahi);
    cudaGetSymbolAddress((void**)&alo, g_alo);
    cudaGetSymbolAddress((void**)&wh,  g_wh);
    cudaGetSymbolAddress((void**)&wl,  g_wl);
    cudaGetSymbolAddress((void**)&woh, g_woh);
    cudaGetSymbolAddress((void**)&wol, g_wol);
    cudaGetSymbolAddress((void**)&qhi, g_qhi);
    cudaGetSymbolAddress((void**)&qlo, g_qlo);
    cudaGetSymbolAddress((void**)&khi, g_khi);
    cudaGetSymbolAddress((void**)&klo, g_klo);
    cudaGetSymbolAddress((void**)&vhi, g_vhi);
    cudaGetSymbolAddress((void**)&vlo, g_vlo);

    cudaFuncSetAttribute(gemm_mma, cudaFuncAttributeMaxDynamicSharedMemorySize, GEMM_SMEM_BYTES);
    cudaFuncSetAttribute(attn_tc,  cudaFuncAttributeMaxDynamicSharedMemorySize, ATT_SMEM_BYTES);

    dim3 blk(256);

    // 0) precision-split preprocessing (Wq|Wkv into one [3072,K] buffer)
    {
        int n8 = MROWS * H_ / 8;
        split_kernel<<<(n8 + 255) / 256, 256>>>(x, xhi, xlo, n8);
        dim3 tb(32, 8);
        splitT_kernel<<<dim3((NH_*D_)/32,    H_/32), tb>>>(Wq,  wh,                     wl,                     H_, NH_*D_);
        splitT_kernel<<<dim3((2*NKV_*D_)/32, H_/32), tb>>>(Wkv, wh + (size_t)2048 * H_, wl + (size_t)2048 * H_, H_, 2*NKV_*D_);
        splitT_kernel<<<dim3(H_/32,          H_/32), tb>>>(Wo,  woh, wol, H_, H_);
    }

    // 1) fused QKV projection (one launch, N=3072)
    gemm_mma<<<dim3(24, 32), blk, GEMM_SMEM_BYTES>>>(xhi, xlo, wh, wl, qkv, MROWS, NQKV, H_);

    // 2) RoPE -> bf16 hi/lo (Q folds softmax scale); V split
    {
        int tq = MROWS * NH_ * 32;
        int tk = MROWS * NKV_ * 32;
        rope_bf16_kernel<<<(tq + 255) / 256, 256>>>(qkv,        NH_,  NQKV, fcos, fsin, qhi, qlo, QSCALE, tq);
        rope_bf16_kernel<<<(tk + 255) / 256, 256>>>(qkv + 2048, NKV_, NQKV, fcos, fsin, khi, klo, 1.0f,   tk);
        int tv = MROWS * 64;
        vsplit_kernel<<<(tv + 255) / 256, 256>>>(qkv, vhi, vlo);
    }

    // 3) attention (tensor-core, split-bf16, writes bf16 hi/lo directly)
    attn_tc<<<dim3(32, 16), blk, ATT_SMEM_BYTES>>>(qhi, qlo, khi, klo, vhi, vlo, ahi, alo, seq);

    // 4) output projection
    gemm_mma<<<dim3(16, 32), blk, GEMM_SMEM_BYTES>>>(ahi, alo, woh, wol, out, MROWS, H_, H_);
}

// round 9
// speedup vs baseline: 2.4211x; 1.0588x over previous
#include <cuda_runtime.h>
#include <cuda_bf16.h>
#include <cstdint>
#include <cstddef>

// Problem constants
#define B_   2
#define S_   2048
#define H_   2048
#define NH_  16
#define NKV_ 4
#define D_   128
#define MROWS (B_*S_)          // 4096
#define NQKV 3072              // 2048 q | 512 k | 512 v
#define QSCALE 0.08838834764831845f

// ---------------------------------------------------------------------------
// PTX helpers (sm_100-safe: mma.sync / ldmatrix / cp.async only)
// ---------------------------------------------------------------------------
__device__ __forceinline__ uint32_t smem_to_u32(const void* p) {
    uint32_t a;
    asm("{ .reg .u64 t; cvta.to.shared.u64 t, %1; cvt.u32.u64 %0, t; }" : "=r"(a) : "l"(p));
    return a;
}
__device__ __forceinline__ void ldsm4(uint32_t* r, uint32_t addr) {
    asm volatile("ldmatrix.sync.aligned.m8n8.x4.shared.b16 {%0,%1,%2,%3}, [%4];"
        : "=r"(r[0]), "=r"(r[1]), "=r"(r[2]), "=r"(r[3]) : "r"(addr));
}
__device__ __forceinline__ void ldsm4t(uint32_t* r, uint32_t addr) {
    asm volatile("ldmatrix.sync.aligned.m8n8.x4.trans.shared.b16 {%0,%1,%2,%3}, [%4];"
        : "=r"(r[0]), "=r"(r[1]), "=r"(r[2]), "=r"(r[3]) : "r"(addr));
}
__device__ __forceinline__ void mma_bf16(float* d, const uint32_t* a, uint32_t b0, uint32_t b1) {
    asm volatile("mma.sync.aligned.m16n8k16.row.col.f32.bf16.bf16.f32 "
        "{%0,%1,%2,%3}, {%4,%5,%6,%7}, {%8,%9}, {%0,%1,%2,%3};"
        : "+f"(d[0]), "+f"(d[1]), "+f"(d[2]), "+f"(d[3])
        : "r"(a[0]), "r"(a[1]), "r"(a[2]), "r"(a[3]), "r"(b0), "r"(b1));
}
__device__ __forceinline__ void cpasync16(uint32_t saddr, const void* g) {
    asm volatile("cp.async.cg.shared.global [%0], [%1], 16;" :: "r"(saddr), "l"(g));
}
#define CP_COMMIT() asm volatile("cp.async.commit_group;" ::: "memory")
#define CP_WAIT(n)  asm volatile("cp.async.wait_group %0;" :: "n"(n) : "memory")

__device__ __forceinline__ void split2pack(float a, float b, uint32_t& hi, uint32_t& lo) {
    __nv_bfloat16 ah = __float2bfloat16_rn(a);
    __nv_bfloat16 bh = __float2bfloat16_rn(b);
    __nv_bfloat16 al = __float2bfloat16_rn(a - __bfloat162float(ah));
    __nv_bfloat16 bl = __float2bfloat16_rn(b - __bfloat162float(bh));
    hi = (uint32_t)(*(uint16_t*)&ah) | ((uint32_t)(*(uint16_t*)&bh) << 16);
    lo = (uint32_t)(*(uint16_t*)&al) | ((uint32_t)(*(uint16_t*)&bl) << 16);
}

// ---------------------------------------------------------------------------
// Scratch (device globals)
// ---------------------------------------------------------------------------
__device__ float g_qkv[(size_t)MROWS * NQKV];        // fp32 q|k|v projections

__device__ __nv_bfloat16 g_xhi[(size_t)MROWS * H_];
__device__ __nv_bfloat16 g_xlo[(size_t)MROWS * H_];
__device__ __nv_bfloat16 g_ahi[(size_t)MROWS * H_];  // attention out (bf16 split)
__device__ __nv_bfloat16 g_alo[(size_t)MROWS * H_];
__device__ __nv_bfloat16 g_wh [(size_t)NQKV * H_];   // [3072,2048] Wq|Wkv transposed
__device__ __nv_bfloat16 g_wl [(size_t)NQKV * H_];
__device__ __nv_bfloat16 g_woh[(size_t)H_ * H_];
__device__ __nv_bfloat16 g_wol[(size_t)H_ * H_];
// attention operands (bf16 hi/lo)
__device__ __nv_bfloat16 g_qhi[(size_t)MROWS * (NH_*D_)];
__device__ __nv_bfloat16 g_qlo[(size_t)MROWS * (NH_*D_)];
__device__ __nv_bfloat16 g_khi[(size_t)MROWS * (NKV_*D_)];
__device__ __nv_bfloat16 g_klo[(size_t)MROWS * (NKV_*D_)];
__device__ __nv_bfloat16 g_vhi[(size_t)MROWS * (NKV_*D_)];
__device__ __nv_bfloat16 g_vlo[(size_t)MROWS * (NKV_*D_)];

// ---------------------------------------------------------------------------
// split fp32 -> bf16 hi/lo (row-major, same layout). 8 elems/thread.
// ---------------------------------------------------------------------------
__global__ void split_kernel(const float* __restrict__ in,
                             __nv_bfloat16* __restrict__ hi,
                             __nv_bfloat16* __restrict__ lo, int n8)
{
    int idx = blockIdx.x * blockDim.x + threadIdx.x;
    if (idx >= n8) return;
    union { __nv_bfloat16 b[8]; uint4 u; } uh, ul;
    const float4* in4 = (const float4*)in;
#pragma unroll
    for (int q = 0; q < 2; q++) {
        float4 v = in4[idx * 2 + q];
        float f[4] = {v.x, v.y, v.z, v.w};
#pragma unroll
        for (int i = 0; i < 4; i++) {
            __nv_bfloat16 h = __float2bfloat16_rn(f[i]);
            uh.b[q * 4 + i] = h;
            ul.b[q * 4 + i] = __float2bfloat16_rn(f[i] - __bfloat162float(h));
        }
    }
    ((uint4*)hi)[idx] = uh.u;
    ((uint4*)lo)[idx] = ul.u;
}

// ---------------------------------------------------------------------------
// split + transpose: W[K,N] fp32 -> Thi/Tlo[N,K] bf16. 32x32 smem tiles.
// ---------------------------------------------------------------------------
__global__ void splitT_kernel(const float* __restrict__ W,
                              __nv_bfloat16* __restrict__ Thi,
                              __nv_bfloat16* __restrict__ Tlo, int K, int N)
{
    __shared__ float s[32][33];
    int tx = threadIdx.x, ty = threadIdx.y;           // (32, 8)
    int n0 = blockIdx.x * 32, k0 = blockIdx.y * 32;
#pragma unroll
    for (int i = 0; i < 4; i++) {
        int k = k0 + ty + i * 8;
        s[ty + i * 8][tx] = W[(size_t)k * N + n0 + tx];
    }
    __syncthreads();
#pragma unroll
    for (int i = 0; i < 4; i++) {
        int n = n0 + ty + i * 8;
        float v = s[tx][ty + i * 8];
        __nv_bfloat16 h = __float2bfloat16_rn(v);
        Thi[(size_t)n * K + k0 + tx] = h;
        Tlo[(size_t)n * K + k0 + tx] = __float2bfloat16_rn(v - __bfloat162float(h));
    }
}

// ---------------------------------------------------------------------------
// mma.sync split-bf16 GEMM: 2-stage cp.async (R3/R5 proven protocol),
// 2 CTAs/SM via 64KB smem + register cap (per-ng B fragment consumption).
// 128x128 CTA tile, BK=32, 8 warps (4x2 -> 32x64 warp tiles).
// ---------------------------------------------------------------------------
#define STAGE_BYTES  32768
#define TILE_BYTES   8192
#define GEMM_SMEM_BYTES (2 * STAGE_BYTES)   // 65536 -> 2 CTAs/SM

__global__ __launch_bounds__(256, 2)
void gemm_mma(const __nv_bfloat16* __restrict__ Ahi, const __nv_bfloat16* __restrict__ Alo,
              const __nv_bfloat16* __restrict__ Bhi, const __nv_bfloat16* __restrict__ Blo,
              float* __restrict__ C, int M, int N, int K)
{
    extern __shared__ char smem[];
    const uint32_t sbase = smem_to_u32(smem);
    const int tid  = threadIdx.x;
    const int wid  = tid >> 5;
    const int lane = tid & 31;
    const int br = blockIdx.y * 128;
    const int bc = blockIdx.x * 128;
    const int wr = wid & 3;
    const int wc = wid >> 2;

    const int nchunks = K >> 5;

    int r0u = (2 * tid) >> 2, u0 = (2 * tid) & 3;
    int r1u = (2 * tid + 1) >> 2, u1 = (2 * tid + 1) & 3;
    uint32_t so0 = (uint32_t)(r0u * 64 + (u0 ^ ((r0u >> 1) & 3)) * 16);
    uint32_t so1 = (uint32_t)(r1u * 64 + (u1 ^ ((r1u >> 1) & 3)) * 16);

    float acc[2][8][4];
#pragma unroll
    for (int i = 0; i < 2; i++)
#pragma unroll
        for (int j = 0; j < 8; j++)
#pragma unroll
            for (int q = 0; q < 4; q++) acc[i][j][q] = 0.f;

    const int arow0 = wr * 32 + (lane & 15);
    const int arow1 = arow0 + 16;
    const int khalf = lane >> 4;

    auto issue_loads = [&](int c, int stage) {
        uint32_t sb = sbase + stage * STAGE_BYTES;
        const __nv_bfloat16* pAh = Ahi + (size_t)br * K + c * 32;
        const __nv_bfloat16* pAl = Alo + (size_t)br * K + c * 32;
        const __nv_bfloat16* pBh = Bhi + (size_t)bc * K + c * 32;
        const __nv_bfloat16* pBl = Blo + (size_t)bc * K + c * 32;
        size_t g0 = (size_t)r0u * K + u0 * 8;
        size_t g1 = (size_t)r1u * K + u1 * 8;
        cpasync16(sb + so0,                  pAh + g0);
        cpasync16(sb + so1,                  pAh + g1);
        cpasync16(sb + TILE_BYTES + so0,     pAl + g0);
        cpasync16(sb + TILE_BYTES + so1,     pAl + g1);
        cpasync16(sb + 2*TILE_BYTES + so0,   pBh + g0);
        cpasync16(sb + 2*TILE_BYTES + so1,   pBh + g1);
        cpasync16(sb + 3*TILE_BYTES + so0,   pBl + g0);
        cpasync16(sb + 3*TILE_BYTES + so1,   pBl + g1);
    };

    issue_loads(0, 0);
    CP_COMMIT();

    for (int c = 0; c < nchunks; c++) {
        if (c + 1 < nchunks) {
            issue_loads(c + 1, (c + 1) & 1);
            CP_COMMIT();
            CP_WAIT(1);
        } else {
            CP_WAIT(0);
        }
        __syncthreads();

        uint32_t sA = sbase + (c & 1) * STAGE_BYTES;
        uint32_t sB = sA + 2 * TILE_BYTES;

#pragma unroll
        for (int kk = 0; kk < 2; kk++) {
            uint32_t ah[2][4], al[2][4];
#pragma unroll
            for (int mt = 0; mt < 2; mt++) {
                int row = (mt ? arow1 : arow0);
                int cc  = (kk * 2 + khalf) ^ ((row >> 1) & 3);
                uint32_t ad = sA + (uint32_t)(row * 64 + cc * 16);
                ldsm4(ah[mt], ad);
                ldsm4(al[mt], ad + TILE_BYTES);
            }
            // per-ng B load + immediate consume (keeps live B regs at 8)
#pragma unroll
            for (int ng = 0; ng < 4; ng++) {
                int row = wc * 64 + ng * 16 + (lane & 15);
                int cc  = (kk * 2 + khalf) ^ ((row >> 1) & 3);
                uint32_t bd = sB + (uint32_t)(row * 64 + cc * 16);
                uint32_t bh[4], bl[4];
                ldsm4(bh, bd);
                ldsm4(bl, bd + TILE_BYTES);
#pragma unroll
                for (int hf = 0; hf < 2; hf++) {
                    int j = 2 * ng + hf;
                    mma_bf16(acc[0][j], ah[0], bh[hf], bh[2 + hf]);
                    mma_bf16(acc[0][j], ah[0], bl[hf], bl[2 + hf]);
                    mma_bf16(acc[0][j], al[0], bh[hf], bh[2 + hf]);
                    mma_bf16(acc[1][j], ah[1], bh[hf], bh[2 + hf]);
                    mma_bf16(acc[1][j], ah[1], bl[hf], bl[2 + hf]);
                    mma_bf16(acc[1][j], al[1], bh[hf], bh[2 + hf]);
                }
            }
        }
        __syncthreads();
    }

#pragma unroll
    for (int mt = 0; mt < 2; mt++) {
        int row = br + wr * 32 + mt * 16 + (lane >> 2);
#pragma unroll
        for (int j = 0; j < 8; j++) {
            int col = bc + wc * 64 + j * 8 + (lane & 3) * 2;
            *(float2*)(C + (size_t)row * N + col) =
                make_float2(acc[mt][j][0], acc[mt][j][1]);
            *(float2*)(C + (size_t)(row + 8) * N + col) =
                make_float2(acc[mt][j][2], acc[mt][j][3]);
        }
    }
}

// ---------------------------------------------------------------------------
// RoPE -> bf16 hi/lo. Q variant folds 1/sqrt(D) scale.
// ---------------------------------------------------------------------------
__global__ void rope_bf16_kernel(const float* __restrict__ buf, int nheads, int ld,
                                 const float* __restrict__ cosT,
                                 const float* __restrict__ sinT,
                                 __nv_bfloat16* __restrict__ ohi,
                                 __nv_bfloat16* __restrict__ olo,
                                 float scale, int total)
{
    int idx = blockIdx.x * blockDim.x + threadIdx.x;
    if (idx >= total) return;
    int d2 = idx & 31;
    int h  = (idx >> 5) % nheads;
    int bs = idx / (32 * nheads);
    int s  = bs & (S_ - 1);
    int d  = d2 * 2;
    const float* p = buf + (size_t)bs * ld + h * D_;
    float x1a = p[d],      x1b = p[d + 1];
    float x2a = p[d + 64], x2b = p[d + 65];
    float ca = cosT[s * D_ + d], cb = cosT[s * D_ + d + 1];
    float sa = sinT[s * D_ + d], sb = sinT[s * D_ + d + 1];
    float o1a = (x1a * ca - x2a * sa) * scale;
    float o1b = (x1b * cb - x2b * sb) * scale;
    float o2a = (x2a * ca + x1a * sa) * scale;
    float o2b = (x2b * cb + x1b * sb) * scale;
    uint32_t h1, l1, h2, l2;
    split2pack(o1a, o1b, h1, l1);
    split2pack(o2a, o2b, h2, l2);
    size_t ob = (size_t)bs * (nheads * D_) + h * D_;
    *(uint32_t*)(ohi + ob + d)      = h1;
    *(uint32_t*)(olo + ob + d)      = l1;
    *(uint32_t*)(ohi + ob + d + 64) = h2;
    *(uint32_t*)(olo + ob + d + 64) = l2;
}

// V split: g_qkv cols [2560,3072) -> vhi/vlo [4096][512]
__global__ void vsplit_kernel(const float* __restrict__ qkv,
                              __nv_bfloat16* __restrict__ vhi,
                              __nv_bfloat16* __restrict__ vlo)
{
    int idx = blockIdx.x * blockDim.x + threadIdx.x;   // 4096*64
    int u8 = idx & 63;
    int r  = idx >> 6;
    const float* src = qkv + (size_t)r * NQKV + 2560 + u8 * 8;
    union { __nv_bfloat16 b[8]; uint4 u; } uh, ul;
#pragma unroll
    for (int q = 0; q < 2; q++) {
        float4 v = *(const float4*)(src + q * 4);
        float f[4] = {v.x, v.y, v.z, v.w};
#pragma unroll
        for (int i = 0; i < 4; i++) {
            __nv_bfloat16 hh = __float2bfloat16_rn(f[i]);
            uh.b[q * 4 + i] = hh;
            ul.b[q * 4 + i] = __float2bfloat16_rn(f[i] - __bfloat162float(hh));
        }
    }
    *(uint4*)(vhi + (size_t)r * 512 + u8 * 8) = uh.u;
    *(uint4*)(vlo + (size_t)r * 512 + u8 * 8) = ul.u;
}

// ---------------------------------------------------------------------------
// Tensor-core flash attention, split-bf16 for QK and PV (unchanged from R6).
// ---------------------------------------------------------------------------
#define A_SQH 0
#define A_SQL 32768
#define A_SKV 65536
#define A_STAGE 65536
#define ATT_SMEM_BYTES (65536 + 2*65536)   // 196608

__global__ __launch_bounds__(256, 1)
void attn_tc(const __nv_bfloat16* __restrict__ qhi, const __nv_bfloat16* __restrict__ qlo,
             const __nv_bfloat16* __restrict__ khi, const __nv_bfloat16* __restrict__ klo,
             const __nv_bfloat16* __restrict__ vhi, const __nv_bfloat16* __restrict__ vlo,
             __nv_bfloat16* __restrict__ Ohi, __nv_bfloat16* __restrict__ Olo,
             const int* __restrict__ seqlen)
{
    extern __shared__ char smem[];
    const uint32_t sb = smem_to_u32(smem);
    const int tid  = threadIdx.x;
    const int wid  = tid >> 5;
    const int lane = tid & 31;
    const int bh = blockIdx.x;                 // 0..31
    const int qt = 15 - blockIdx.y;            // heavy tiles first
    const int b   = bh >> 4;
    const int h   = bh & 15;
    const int kvh = h >> 2;
    const int q0  = qt * 128;
    const int len = seqlen[b];

    // ---- load Q tile (hi/lo), 128 rows x 16 units each ----
    {
        const __nv_bfloat16* qh = qhi + (size_t)(b * S_ + q0) * (NH_*D_) + h * D_;
        const __nv_bfloat16* ql = qlo + (size_t)(b * S_ + q0) * (NH_*D_) + h * D_;
#pragma unroll
        for (int i = 0; i < 8; i++) {
            int g = i * 256 + tid;
            int r = g >> 4, u = g & 15;
            uint32_t so = (uint32_t)(r * 256 + ((u ^ (r & 7)) * 16));
            size_t go = (size_t)r * (NH_*D_) + u * 8;
            cpasync16(sb + A_SQH + so, qh + go);
            cpasync16(sb + A_SQL + so, ql + go);
        }
    }

    const int e  = min(q0 + 128, len);
    const int nt = (e + 63) >> 6;

    auto load_kv = [&](int t, int stage) {
        uint32_t st = sb + A_SKV + stage * A_STAGE;
        size_t base = (size_t)(b * S_ + t * 64) * (NKV_*D_) + kvh * D_;
#pragma unroll
        for (int i = 0; i < 4; i++) {
            int g = i * 256 + tid;
            int r = g >> 4, u = g & 15;
            uint32_t so = (uint32_t)(r * 256 + ((u ^ (r & 7)) * 16));
            size_t go = base + (size_t)r * (NKV_*D_) + u * 8;
            cpasync16(st + so,         khi + go);
            cpasync16(st + 16384 + so, klo + go);
            cpasync16(st + 32768 + so, vhi + go);
            cpasync16(st + 49152 + so, vlo + go);
        }
    };

    load_kv(0, 0);
    CP_COMMIT();

    float out[16][4];
#pragma unroll
    for (int j = 0; j < 16; j++)
#pragma unroll
        for (int q = 0; q < 4; q++) out[j][q] = 0.f;
    float m0 = -1e30f, m1 = -1e30f, l0 = 0.f, l1 = 0.f;

    const int wrow = q0 + wid * 16;            // warp's first q row (global)

    for (int t = 0; t < nt; t++) {
        if (t + 1 < nt) { load_kv(t + 1, (t + 1) & 1); CP_COMMIT(); CP_WAIT(1); }
        else            { CP_WAIT(0); }
        __syncthreads();

        const int k0 = t * 64;
        if (k0 <= wrow + 15) {                 // warp has at least one unmasked row
            uint32_t sK = sb + A_SKV + (t & 1) * A_STAGE;
            uint32_t sV = sK + 32768;

            // ---- scores S = Q K^T (m16 x 64) ----
            float s[8][4];
#pragma unroll
            for (int j = 0; j < 8; j++)
#pragma unroll
                for (int q = 0; q < 4; q++) s[j][q] = 0.f;

#pragma unroll
            for (int kk = 0; kk < 8; kk++) {
                int ar = wid * 16 + (lane & 15);
                int au = 2 * kk + (lane >> 4);
                uint32_t aso = (uint32_t)(ar * 256 + ((au ^ (ar & 7)) * 16));
                uint32_t ah[4], al[4];
                ldsm4(ah, sb + A_SQH + aso);
                ldsm4(al, sb + A_SQL + aso);
#pragma unroll
                for (int ng = 0; ng < 4; ng++) {
                    int br = ng * 16 + (lane & 15);
                    uint32_t bso = (uint32_t)(br * 256 + ((au ^ (br & 7)) * 16));
                    uint32_t bhf[4], blf[4];
                    ldsm4(bhf, sK + bso);
                    ldsm4(blf, sK + 16384 + bso);
#pragma unroll
                    for (int hf = 0; hf < 2; hf++) {
                        int j = 2 * ng + hf;
                        mma_bf16(s[j], ah, bhf[hf], bhf[2 + hf]);
                        mma_bf16(s[j], ah, blf[hf], blf[2 + hf]);
                        mma_bf16(s[j], al, bhf[hf], bhf[2 + hf]);
                    }
                }
            }

            // ---- mask ----
            const int qr0 = wrow + (lane >> 2);
            bool fullvalid = (k0 + 63 <= wrow) && (k0 + 63 < len);
            if (!fullvalid) {
#pragma unroll
                for (int j = 0; j < 8; j++) {
                    int kgb = k0 + j * 8 + (lane & 3) * 2;
#pragma unroll
                    for (int q = 0; q < 4; q++) {
                        int kg = kgb + (q & 1);
                        int qg = qr0 + ((q >> 1) << 3);
                        if (kg > qg || kg >= len) s[j][q] = -1e30f;
                    }
                }
            }

            // ---- online softmax ----
            float mx0 = -1e30f, mx1 = -1e30f;
#pragma unroll
            for (int j = 0; j < 8; j++) {
                mx0 = fmaxf(mx0, fmaxf(s[j][0], s[j][1]));
                mx1 = fmaxf(mx1, fmaxf(s[j][2], s[j][3]));
            }
#pragma unroll
            for (int off = 1; off <= 2; off <<= 1) {
                mx0 = fmaxf(mx0, __shfl_xor_sync(0xffffffffu, mx0, off));
                mx1 = fmaxf(mx1, __shfl_xor_sync(0xffffffffu, mx1, off));
            }
            float nm0 = fmaxf(m0, mx0), nm1 = fmaxf(m1, mx1);
            float sc0 = __expf(m0 - nm0), sc1 = __expf(m1 - nm1);
            m0 = nm0; m1 = nm1;
            float sum0 = 0.f, sum1 = 0.f;
#pragma unroll
            for (int j = 0; j < 8; j++) {
                s[j][0] = __expf(s[j][0] - nm0);
                s[j][1] = __expf(s[j][1] - nm0);
                s[j][2] = __expf(s[j][2] - nm1);
                s[j][3] = __expf(s[j][3] - nm1);
                sum0 += s[j][0] + s[j][1];
                sum1 += s[j][2] + s[j][3];
            }
#pragma unroll
            for (int off = 1; off <= 2; off <<= 1) {
                sum0 += __shfl_xor_sync(0xffffffffu, sum0, off);
                sum1 += __shfl_xor_sync(0xffffffffu, sum1, off);
            }
            l0 = l0 * sc0 + sum0;
            l1 = l1 * sc1 + sum1;
#pragma unroll
            for (int j = 0; j < 16; j++) {
                out[j][0] *= sc0; out[j][1] *= sc0;
                out[j][2] *= sc1; out[j][3] *= sc1;
            }

            // ---- PV: out += P V ----
#pragma unroll
            for (int jk = 0; jk < 4; jk++) {
                uint32_t ph[4], pl[4];
                split2pack(s[2*jk][0],   s[2*jk][1],   ph[0], pl[0]);
                split2pack(s[2*jk][2],   s[2*jk][3],   ph[1], pl[1]);
                split2pack(s[2*jk+1][0], s[2*jk+1][1], ph[2], pl[2]);
                split2pack(s[2*jk+1][2], s[2*jk+1][3], ph[3], pl[3]);
#pragma unroll
                for (int gn = 0; gn < 8; gn++) {
                    int vr = jk * 16 + (lane & 15);
                    int vu = 2 * gn + (lane >> 4);
                    uint32_t vso = (uint32_t)(vr * 256 + ((vu ^ (vr & 7)) * 16));
                    uint32_t vh4[4], vl4[4];
                    ldsm4t(vh4, sV + vso);
                    ldsm4t(vl4, sV + 16384 + vso);
#pragma unroll
                    for (int hf = 0; hf < 2; hf++) {
                        int jn = 2 * gn + hf;
                        mma_bf16(out[jn], ph, vh4[2*hf], vh4[2*hf + 1]);
                        mma_bf16(out[jn], pl, vh4[2*hf], vh4[2*hf + 1]);
                        mma_bf16(out[jn], ph, vl4[2*hf], vl4[2*hf + 1]);
                    }
                }
            }
        }
        __syncthreads();
    }

    // ---- epilogue: normalize, split to bf16 hi/lo, store ----
    float i0 = 1.0f / l0, i1 = 1.0f / l1;
    size_t ro0 = (size_t)(b * S_ + wrow + (lane >> 2)) * (NH_*D_) + h * D_;
    size_t ro1 = ro0 + (size_t)8 * (NH_*D_);
#pragma unroll
    for (int jn = 0; jn < 16; jn++) {
        int col = jn * 8 + (lane & 3) * 2;
        uint32_t hh, ll;
        split2pack(out[jn][0] * i0, out[jn][1] * i0, hh, ll);
        *(uint32_t*)(Ohi + ro0 + col) = hh;
        *(uint32_t*)(Olo + ro0 + col) = ll;
        split2pack(out[jn][2] * i1, out[jn][3] * i1, hh, ll);
        *(uint32_t*)(Ohi + ro1 + col) = hh;
        *(uint32_t*)(Olo + ro1 + col) = ll;
    }
}

// ---------------------------------------------------------------------------
// Launch
// ---------------------------------------------------------------------------
extern "C" void kernel_launch(void* const* d_in, const int* in_sizes, int n_in,
                              void* d_out, int out_size)
{
    const float* x    = (const float*)d_in[0];
    const int*   seq  = (const int*)  d_in[1];
    const float* fcos = (const float*)d_in[2];
    const float* fsin = (const float*)d_in[3];
    const float* Wq   = (const float*)d_in[4];
    const float* Wkv  = (const float*)d_in[5];
    const float* Wo   = (const float*)d_in[6];
    float* out = (float*)d_out;

    float *qkv;
    cudaGetSymbolAddress((void**)&qkv, g_qkv);
    __nv_bfloat16 *xhi, *xlo, *ahi, *alo, *wh, *wl, *woh, *wol;
    __nv_bfloat16 *qhi, *qlo, *khi, *klo, *vhi, *vlo;
    cudaGetSymbolAddress((void**)&xhi, g_xhi);
    cudaGetSymbolAddress((void**)&xlo, g_xlo);
    cudaGetSymbolAddress((void**)&ahi, g_ahi);
    cudaGetSymbolAddress((void**)&alo, g_alo);
    cudaGetSymbolAddress((void**)&wh,  g_wh);
    cudaGetSymbolAddress((void**)&wl,  g_wl);
    cudaGetSymbolAddress((void**)&woh, g_woh);
    cudaGetSymbolAddress((void**)&wol, g_wol);
    cudaGetSymbolAddress((void**)&qhi, g_qhi);
    cudaGetSymbolAddress((void**)&qlo, g_qlo);
    cudaGetSymbolAddress((void**)&khi, g_khi);
    cudaGetSymbolAddress((void**)&klo, g_klo);
    cudaGetSymbolAddress((void**)&vhi, g_vhi);
    cudaGetSymbolAddress((void**)&vlo, g_vlo);

    cudaFuncSetAttribute(gemm_mma, cudaFuncAttributeMaxDynamicSharedMemorySize, GEMM_SMEM_BYTES);
    cudaFuncSetAttribute(attn_tc,  cudaFuncAttributeMaxDynamicSharedMemorySize, ATT_SMEM_BYTES);

    dim3 blk(256);

    // 0) precision-split preprocessing (Wq|Wkv into one [3072,K] buffer)
    {
        int n8 = MROWS * H_ / 8;
        split_kernel<<<(n8 + 255) / 256, 256>>>(x, xhi, xlo, n8);
        dim3 tb(32, 8);
        splitT_kernel<<<dim3((NH_*D_)/32,    H_/32), tb>>>(Wq,  wh,                     wl,                     H_, NH_*D_);
        splitT_kernel<<<dim3((2*NKV_*D_)/32, H_/32), tb>>>(Wkv, wh + (size_t)2048 * H_, wl + (size_t)2048 * H_, H_, 2*NKV_*D_);
        splitT_kernel<<<dim3(H_/32,          H_/32), tb>>>(Wo,  woh, wol, H_, H_);
    }

    // 1) fused QKV projection (one launch, N=3072)
    gemm_mma<<<dim3(24, 32), blk, GEMM_SMEM_BYTES>>>(xhi, xlo, wh, wl, qkv, MROWS, NQKV, H_);

    // 2) RoPE -> bf16 hi/lo (Q folds softmax scale); V split
    {
        int tq = MROWS * NH_ * 32;
        int tk = MROWS * NKV_ * 32;
        rope_bf16_kernel<<<(tq + 255) / 256, 256>>>(qkv,        NH_,  NQKV, fcos, fsin, qhi, qlo, QSCALE, tq);
        rope_bf16_kernel<<<(tk + 255) / 256, 256>>>(qkv + 2048, NKV_, NQKV, fcos, fsin, khi, klo, 1.0f,   tk);
        int tv = MROWS * 64;
        vsplit_kernel<<<(tv + 255) / 256, 256>>>(qkv, vhi, vlo);
    }

    // 3) attention (tensor-core, split-bf16, writes bf16 hi/lo directly)
    attn_tc<<<dim3(32, 16), blk, ATT_SMEM_BYTES>>>(qhi, qlo, khi, klo, vhi, vlo, ahi, alo, seq);

    // 4) output projection
    gemm_mma<<<dim3(16, 32), blk, GEMM_SMEM_BYTES>>>(ahi, alo, woh, wol, out, MROWS, H_, H_);
}